// round 1
// baseline (speedup 1.0000x reference)
#include <cuda_runtime.h>

#define BDIM 1024
#define NH 16
#define HD 64
#define BB 2
#define SEQ 2048
#define MTOT (BB*SEQ)            // 4096 rows
#define ATT_SCALE 0.125f         // 1/sqrt(64)

// Scratch (static device globals — allocation-guard safe). 16 MB each.
__device__ float g_Q[(long)BB*NH*SEQ*HD];
__device__ float g_K[(long)BB*NH*SEQ*HD];
__device__ float g_V[(long)BB*NH*SEQ*HD];
__device__ float g_O[(long)MTOT*BDIM];

// ---------------------------------------------------------------------------
// SGEMM: C[M,Nout] = A[M,K] @ W[Nout,K]^T + bias[Nout]
// 128x128 block tile, 8-deep K tile, 256 threads, 8x8 register micro-tile.
// MODE 0: A = x, epilogue scatters into g_Q/g_K/g_V as [B,H,N,Dh]
// MODE 1: A = g_O (ignores A arg), epilogue writes C row-major
// ---------------------------------------------------------------------------
template<int MODE>
__global__ __launch_bounds__(256)
void sgemm_kernel(const float* __restrict__ A, const float* __restrict__ W,
                  const float* __restrict__ bias, float* __restrict__ C,
                  int K, int Nout)
{
    __shared__ float As[8][128];
    __shared__ float Bs[8][128];

    const float* Abase = (MODE == 1) ? (const float*)g_O : A;

    int tid = threadIdx.x;
    int tx = tid & 15;
    int ty = tid >> 4;
    int m0 = blockIdx.y * 128;
    int n0 = blockIdx.x * 128;

    int lrow = tid >> 1;         // 0..127
    int lcol = (tid & 1) * 4;    // 0 or 4

    const float* Aptr = Abase + (long)(m0 + lrow) * K + lcol;
    const float* Wptr = W     + (long)(n0 + lrow) * K + lcol;

    float acc[8][8];
    #pragma unroll
    for (int i = 0; i < 8; i++)
        #pragma unroll
        for (int j = 0; j < 8; j++) acc[i][j] = 0.f;

    for (int k0 = 0; k0 < K; k0 += 8) {
        float4 av = *(const float4*)(Aptr + k0);
        float4 wv = *(const float4*)(Wptr + k0);
        As[lcol+0][lrow] = av.x; As[lcol+1][lrow] = av.y;
        As[lcol+2][lrow] = av.z; As[lcol+3][lrow] = av.w;
        Bs[lcol+0][lrow] = wv.x; Bs[lcol+1][lrow] = wv.y;
        Bs[lcol+2][lrow] = wv.z; Bs[lcol+3][lrow] = wv.w;
        __syncthreads();

        #pragma unroll
        for (int kk = 0; kk < 8; kk++) {
            float af[8], bf[8];
            *(float4*)&af[0] = *(const float4*)&As[kk][ty*8];
            *(float4*)&af[4] = *(const float4*)&As[kk][ty*8+4];
            *(float4*)&bf[0] = *(const float4*)&Bs[kk][tx*8];
            *(float4*)&bf[4] = *(const float4*)&Bs[kk][tx*8+4];
            #pragma unroll
            for (int i = 0; i < 8; i++)
                #pragma unroll
                for (int j = 0; j < 8; j++)
                    acc[i][j] += af[i] * bf[j];
        }
        __syncthreads();
    }

    // Epilogue
    #pragma unroll
    for (int i = 0; i < 8; i++) {
        int row = m0 + ty*8 + i;
        #pragma unroll
        for (int j = 0; j < 8; j++) {
            int col = n0 + tx*8 + j;
            float v = acc[i][j] + bias[col];
            if (MODE == 0) {
                int b = row >> 11;            // /2048
                int n = row & (SEQ - 1);
                int which = col >> 10;        // 0=Q,1=K,2=V
                int c = col & (BDIM - 1);
                int h = c >> 6;
                int d = c & 63;
                long idx = ((((long)b*NH + h)*SEQ) + n)*HD + d;
                if (which == 0)      g_Q[idx] = v;
                else if (which == 1) g_K[idx] = v;
                else                 g_V[idx] = v;
            } else {
                C[(long)row * Nout + col] = v;
            }
        }
    }
}

// ---------------------------------------------------------------------------
// Flash attention: one block = 128 q-rows of one (b,h).
// q (scaled) and output accumulator live in registers; K/V tiles of 64 keys
// staged in smem (broadcast reads). Online softmax over 16-key subtiles.
// Writes output already transposed to [B, N, H*Dh] for the projection GEMM.
// ---------------------------------------------------------------------------
__global__ __launch_bounds__(128)
void attn_kernel()
{
    __shared__ float Ksh[64 * HD];
    __shared__ float Vsh[64 * HD];

    int t = threadIdx.x;
    int b = blockIdx.z;
    int h = blockIdx.y;
    int qrow = blockIdx.x * 128 + t;

    const float* Qb = g_Q + ((long)(b*NH + h)) * SEQ * HD;
    const float* Kb = g_K + ((long)(b*NH + h)) * SEQ * HD;
    const float* Vb = g_V + ((long)(b*NH + h)) * SEQ * HD;

    float q[HD];
    #pragma unroll
    for (int d4 = 0; d4 < 16; d4++) {
        float4 qv = *(const float4*)(Qb + (long)qrow*HD + d4*4);
        q[4*d4+0] = qv.x * ATT_SCALE;
        q[4*d4+1] = qv.y * ATT_SCALE;
        q[4*d4+2] = qv.z * ATT_SCALE;
        q[4*d4+3] = qv.w * ATT_SCALE;
    }

    float m = -1e30f, l = 0.f;
    float acc[HD];
    #pragma unroll
    for (int d = 0; d < HD; d++) acc[d] = 0.f;

    for (int kt = 0; kt < SEQ/64; kt++) {
        __syncthreads();
        {
            const float4* srcK = (const float4*)(Kb + (long)kt*64*HD);
            const float4* srcV = (const float4*)(Vb + (long)kt*64*HD);
            float4* dK = (float4*)Ksh;
            float4* dV = (float4*)Vsh;
            #pragma unroll
            for (int i = 0; i < 8; i++) {
                dK[t + i*128] = srcK[t + i*128];
                dV[t + i*128] = srcV[t + i*128];
            }
        }
        __syncthreads();

        #pragma unroll 1
        for (int j0 = 0; j0 < 64; j0 += 16) {
            float s[16];
            // scores for 16 keys
            #pragma unroll
            for (int jj = 0; jj < 16; jj++) {
                const float4* kr = (const float4*)(Ksh + (j0 + jj)*HD);
                float a0 = 0.f, a1 = 0.f, a2 = 0.f, a3 = 0.f;
                #pragma unroll
                for (int d4 = 0; d4 < 16; d4++) {
                    float4 kv = kr[d4];
                    a0 += q[4*d4+0] * kv.x;
                    a1 += q[4*d4+1] * kv.y;
                    a2 += q[4*d4+2] * kv.z;
                    a3 += q[4*d4+3] * kv.w;
                }
                s[jj] = (a0 + a1) + (a2 + a3);
            }
            // online softmax update
            float mloc = s[0];
            #pragma unroll
            for (int jj = 1; jj < 16; jj++) mloc = fmaxf(mloc, s[jj]);
            float m_new = fmaxf(m, mloc);
            float corr = __expf(m - m_new);
            l *= corr;
            #pragma unroll
            for (int d = 0; d < HD; d++) acc[d] *= corr;
            #pragma unroll
            for (int jj = 0; jj < 16; jj++) {
                float p = __expf(s[jj] - m_new);
                l += p;
                s[jj] = p;
            }
            m = m_new;
            // P @ V
            #pragma unroll
            for (int jj = 0; jj < 16; jj++) {
                float p = s[jj];
                const float4* vr = (const float4*)(Vsh + (j0 + jj)*HD);
                #pragma unroll
                for (int d4 = 0; d4 < 16; d4++) {
                    float4 vv = vr[d4];
                    acc[4*d4+0] += p * vv.x;
                    acc[4*d4+1] += p * vv.y;
                    acc[4*d4+2] += p * vv.z;
                    acc[4*d4+3] += p * vv.w;
                }
            }
        }
    }

    float inv = 1.f / l;
    float* Ob = g_O + ((long)(b*SEQ) + qrow)*BDIM + h*HD;
    #pragma unroll
    for (int d4 = 0; d4 < 16; d4++) {
        float4 o;
        o.x = acc[4*d4+0] * inv;
        o.y = acc[4*d4+1] * inv;
        o.z = acc[4*d4+2] * inv;
        o.w = acc[4*d4+3] * inv;
        *(float4*)(Ob + 4*d4) = o;
    }
}

// ---------------------------------------------------------------------------
// Launch: QKV GEMM -> attention -> projection GEMM (default stream, in order)
// ---------------------------------------------------------------------------
extern "C" void kernel_launch(void* const* d_in, const int* in_sizes, int n_in,
                              void* d_out, int out_size)
{
    const float* x      = (const float*)d_in[0];
    const float* qkv_w  = (const float*)d_in[1];
    const float* qkv_b  = (const float*)d_in[2];
    const float* proj_w = (const float*)d_in[3];
    const float* proj_b = (const float*)d_in[4];
    float* out = (float*)d_out;

    dim3 g_qkv(3*BDIM/128, MTOT/128);   // (24, 32)
    sgemm_kernel<0><<<g_qkv, 256>>>(x, qkv_w, qkv_b, nullptr, BDIM, 3*BDIM);

    dim3 g_attn(SEQ/128, NH, BB);       // (16, 16, 2)
    attn_kernel<<<g_attn, 128>>>();

    dim3 g_proj(BDIM/128, MTOT/128);    // (8, 32)
    sgemm_kernel<1><<<g_proj, 256>>>(nullptr, proj_w, proj_b, out, BDIM, BDIM);
}

// round 2
// speedup vs baseline: 3.2232x; 3.2232x over previous
#include <cuda_runtime.h>
#include <cstdint>

#define BDIM 1024
#define NH 16
#define HD 64
#define BB 2
#define SEQ 2048
#define MTOT (BB*SEQ)
// 0.125 * log2(e): fold softmax scale + exp2 conversion into Q
#define QK_SCALE 0.1803368801111204f

__device__ float g_Q[(long)BB*NH*SEQ*HD];
__device__ float g_K[(long)BB*NH*SEQ*HD];
__device__ float g_V[(long)BB*NH*SEQ*HD];
__device__ float g_O[(long)MTOT*BDIM];

// ---------------------------------------------------------------------------
// helpers
// ---------------------------------------------------------------------------
__device__ __forceinline__ uint32_t f2tf32(float f) {
    uint32_t u;
    asm("cvt.rna.tf32.f32 %0, %1;" : "=r"(u) : "f"(f));
    return u;
}

__device__ __forceinline__ void mma_tf32(float c[4],
                                         uint32_t a0, uint32_t a1, uint32_t a2, uint32_t a3,
                                         uint32_t b0, uint32_t b1) {
    asm volatile(
        "mma.sync.aligned.m16n8k8.row.col.f32.tf32.tf32.f32 "
        "{%0,%1,%2,%3}, {%4,%5,%6,%7}, {%8,%9}, {%0,%1,%2,%3};"
        : "+f"(c[0]), "+f"(c[1]), "+f"(c[2]), "+f"(c[3])
        : "r"(a0), "r"(a1), "r"(a2), "r"(a3), "r"(b0), "r"(b1));
}

__device__ __forceinline__ void sts_tf32x4(uint32_t* p, float4 v) {
    uint4 u;
    u.x = f2tf32(v.x); u.y = f2tf32(v.y); u.z = f2tf32(v.z); u.w = f2tf32(v.w);
    *(uint4*)p = u;
}

// ---------------------------------------------------------------------------
// TF32 GEMM: C[M,Nout] = A[M,K] @ W[Nout,K]^T + bias
// block 128x128, Ktile 16, 256 threads (8 warps, 2x4), warp tile 64x32.
// smem stride 20 floats -> fragment LDS conflict-free (20 mod 32 pattern).
// MODE 0: epilogue scatters to g_Q/g_K/g_V [B,H,N,Dh]; MODE 1: row-major C.
// ---------------------------------------------------------------------------
#define SA 20
template<int MODE>
__global__ __launch_bounds__(256, 2)
void gemm_tf32(const float* __restrict__ A, const float* __restrict__ W,
               const float* __restrict__ bias, float* __restrict__ Cout,
               int K, int Nout)
{
    __shared__ __align__(16) uint32_t As[2][128*SA];
    __shared__ __align__(16) uint32_t Bs[2][128*SA];

    const float* Abase = (MODE == 1) ? (const float*)g_O : A;

    int tid  = threadIdx.x;
    int lane = tid & 31, warp = tid >> 5;
    int g = lane >> 2, t = lane & 3;
    int wm = (warp >> 2) * 64, wn = (warp & 3) * 32;
    int m0 = blockIdx.y * 128, n0 = blockIdx.x * 128;

    // staging: each thread 2 float4 of A + 2 of W per Ktile
    int r0 = tid >> 2;          // 0..63
    int c0 = (tid & 3) * 4;     // 0,4,8,12
    const float* Ap0 = Abase + (long)(m0 + r0) * K + c0;
    const float* Ap1 = Abase + (long)(m0 + r0 + 64) * K + c0;
    const float* Wp0 = W + (long)(n0 + r0) * K + c0;
    const float* Wp1 = W + (long)(n0 + r0 + 64) * K + c0;

    float4 ra0 = *(const float4*)Ap0;
    float4 ra1 = *(const float4*)Ap1;
    float4 rb0 = *(const float4*)Wp0;
    float4 rb1 = *(const float4*)Wp1;

    float acc[4][4][4];
    #pragma unroll
    for (int i = 0; i < 4; i++)
        #pragma unroll
        for (int j = 0; j < 4; j++)
            #pragma unroll
            for (int q = 0; q < 4; q++) acc[i][j][q] = 0.f;

    int iters = K >> 4;
    for (int it = 0; it < iters; ++it) {
        uint32_t* as = As[it & 1];
        uint32_t* bs = Bs[it & 1];
        sts_tf32x4(as + r0*SA + c0, ra0);
        sts_tf32x4(as + (r0+64)*SA + c0, ra1);
        sts_tf32x4(bs + r0*SA + c0, rb0);
        sts_tf32x4(bs + (r0+64)*SA + c0, rb1);
        __syncthreads();

        if (it + 1 < iters) {
            int kn = (it + 1) << 4;
            ra0 = *(const float4*)(Ap0 + kn);
            ra1 = *(const float4*)(Ap1 + kn);
            rb0 = *(const float4*)(Wp0 + kn);
            rb1 = *(const float4*)(Wp1 + kn);
        }

        #pragma unroll
        for (int kk = 0; kk < 16; kk += 8) {
            uint32_t af[4][4], bf[4][2];
            #pragma unroll
            for (int mt = 0; mt < 4; mt++) {
                int rw = wm + mt*16;
                af[mt][0] = as[(rw+g)*SA   + kk + t];
                af[mt][1] = as[(rw+g+8)*SA + kk + t];
                af[mt][2] = as[(rw+g)*SA   + kk + t + 4];
                af[mt][3] = as[(rw+g+8)*SA + kk + t + 4];
            }
            #pragma unroll
            for (int nt = 0; nt < 4; nt++) {
                int cw = wn + nt*8 + g;
                bf[nt][0] = bs[cw*SA + kk + t];
                bf[nt][1] = bs[cw*SA + kk + t + 4];
            }
            #pragma unroll
            for (int mt = 0; mt < 4; mt++)
                #pragma unroll
                for (int nt = 0; nt < 4; nt++)
                    mma_tf32(acc[mt][nt], af[mt][0], af[mt][1], af[mt][2], af[mt][3],
                             bf[nt][0], bf[nt][1]);
        }
        __syncthreads();
    }

    // epilogue
    #pragma unroll
    for (int mt = 0; mt < 4; mt++) {
        int rowA = m0 + wm + mt*16 + g;
        int rowB = rowA + 8;
        #pragma unroll
        for (int nt = 0; nt < 4; nt++) {
            int col = n0 + wn + nt*8 + 2*t;
            float b0v = bias[col], b1v = bias[col+1];
            float2 va = make_float2(acc[mt][nt][0] + b0v, acc[mt][nt][1] + b1v);
            float2 vb = make_float2(acc[mt][nt][2] + b0v, acc[mt][nt][3] + b1v);
            if (MODE == 0) {
                int which = col >> 10;
                int c = col & (BDIM - 1);
                int hh = c >> 6, d = c & 63;
                float* dst = (which == 0) ? g_Q : (which == 1) ? g_K : g_V;
                {
                    int b = rowA >> 11, n = rowA & (SEQ - 1);
                    long idx = ((((long)b*NH + hh)*SEQ) + n)*HD + d;
                    *(float2*)(dst + idx) = va;
                }
                {
                    int b = rowB >> 11, n = rowB & (SEQ - 1);
                    long idx = ((((long)b*NH + hh)*SEQ) + n)*HD + d;
                    *(float2*)(dst + idx) = vb;
                }
            } else {
                *(float2*)(Cout + (long)rowA * Nout + col) = va;
                *(float2*)(Cout + (long)rowB * Nout + col) = vb;
            }
        }
    }
}

// ---------------------------------------------------------------------------
// TF32 flash attention. Block = 128 q rows of one (b,h), 8 warps x 16 rows.
// Q fragments in registers (pre-scaled by 0.125*log2e). K/V staged in smem
// as tf32; strides 68 (K, pattern g*stride+t) and 72 (V, pattern t*stride+g)
// keep both B-fragment patterns bank-conflict-free. P goes C-frag -> A-frag
// via quad shuffles (no smem round trip). exp2f softmax.
// ---------------------------------------------------------------------------
#define KSD 68
#define VSD 72
__global__ __launch_bounds__(256)
void attn_tf32()
{
    __shared__ __align__(16) uint32_t Ks[64*KSD];
    __shared__ __align__(16) uint32_t Vs[64*VSD];

    int tid  = threadIdx.x;
    int lane = tid & 31, warp = tid >> 5;
    int g = lane >> 2, t = lane & 3;
    int b = blockIdx.z, h = blockIdx.y;
    long base = ((long)(b*NH + h)) * SEQ * HD;
    const float* Qb = g_Q + base;
    const float* Kb = g_K + base;
    const float* Vb = g_V + base;

    int qn = blockIdx.x * 128 + warp * 16;

    // Q fragments (registers, whole kernel)
    uint32_t qf[8][4];
    {
        const float* q0 = Qb + (long)(qn + g) * HD;
        const float* q1 = Qb + (long)(qn + g + 8) * HD;
        #pragma unroll
        for (int kk = 0; kk < 8; kk++) {
            int c = kk*8 + t;
            qf[kk][0] = f2tf32(q0[c]     * QK_SCALE);
            qf[kk][1] = f2tf32(q1[c]     * QK_SCALE);
            qf[kk][2] = f2tf32(q0[c+4]   * QK_SCALE);
            qf[kk][3] = f2tf32(q1[c+4]   * QK_SCALE);
        }
    }

    float oacc[8][4];
    #pragma unroll
    for (int i = 0; i < 8; i++)
        #pragma unroll
        for (int j = 0; j < 4; j++) oacc[i][j] = 0.f;
    float mA = -1e30f, mB = -1e30f, lA = 0.f, lB = 0.f;

    // staging regs: 4 float4 K + 4 float4 V per thread per tile
    float4 rk[4], rv[4];
    {
        const float4* ks = (const float4*)Kb;
        const float4* vs = (const float4*)Vb;
        #pragma unroll
        for (int i = 0; i < 4; i++) { rk[i] = ks[tid + i*256]; rv[i] = vs[tid + i*256]; }
    }

    for (int kt = 0; kt < SEQ/64; ++kt) {
        #pragma unroll
        for (int i = 0; i < 4; i++) {
            int id = tid + i*256;
            int row = id >> 4, c4 = (id & 15) * 4;
            sts_tf32x4(&Ks[row*KSD + c4], rk[i]);
            sts_tf32x4(&Vs[row*VSD + c4], rv[i]);
        }
        __syncthreads();

        if (kt + 1 < SEQ/64) {
            const float4* ks = (const float4*)(Kb + (long)(kt+1)*64*HD);
            const float4* vs = (const float4*)(Vb + (long)(kt+1)*64*HD);
            #pragma unroll
            for (int i = 0; i < 4; i++) { rk[i] = ks[tid + i*256]; rv[i] = vs[tid + i*256]; }
        }

        // S = Q @ K^T (in log2 units)
        float sc[8][4];
        #pragma unroll
        for (int i = 0; i < 8; i++)
            #pragma unroll
            for (int j = 0; j < 4; j++) sc[i][j] = 0.f;
        #pragma unroll
        for (int kk = 0; kk < 8; kk++) {
            #pragma unroll
            for (int nt = 0; nt < 8; nt++) {
                uint32_t b0 = Ks[(nt*8+g)*KSD + kk*8 + t];
                uint32_t b1 = Ks[(nt*8+g)*KSD + kk*8 + t + 4];
                mma_tf32(sc[nt], qf[kk][0], qf[kk][1], qf[kk][2], qf[kk][3], b0, b1);
            }
        }

        // online softmax (rows g and g+8, per-quad stats)
        float mlA = -1e30f, mlB = -1e30f;
        #pragma unroll
        for (int nt = 0; nt < 8; nt++) {
            mlA = fmaxf(mlA, fmaxf(sc[nt][0], sc[nt][1]));
            mlB = fmaxf(mlB, fmaxf(sc[nt][2], sc[nt][3]));
        }
        mlA = fmaxf(mlA, __shfl_xor_sync(0xffffffffu, mlA, 1));
        mlA = fmaxf(mlA, __shfl_xor_sync(0xffffffffu, mlA, 2));
        mlB = fmaxf(mlB, __shfl_xor_sync(0xffffffffu, mlB, 1));
        mlB = fmaxf(mlB, __shfl_xor_sync(0xffffffffu, mlB, 2));
        float mnA = fmaxf(mA, mlA), mnB = fmaxf(mB, mlB);
        float cA = exp2f(mA - mnA), cB = exp2f(mB - mnB);
        lA *= cA; lB *= cB;
        #pragma unroll
        for (int nt = 0; nt < 8; nt++) {
            oacc[nt][0] *= cA; oacc[nt][1] *= cA;
            oacc[nt][2] *= cB; oacc[nt][3] *= cB;
        }
        #pragma unroll
        for (int nt = 0; nt < 8; nt++) {
            float p0 = exp2f(sc[nt][0] - mnA);
            float p1 = exp2f(sc[nt][1] - mnA);
            float p2 = exp2f(sc[nt][2] - mnB);
            float p3 = exp2f(sc[nt][3] - mnB);
            lA += p0 + p1; lB += p2 + p3;
            sc[nt][0] = p0; sc[nt][1] = p1; sc[nt][2] = p2; sc[nt][3] = p3;
        }
        mA = mnA; mB = mnB;

        // O += P @ V ; P C-frag -> A-frag via quad shuffles
        #pragma unroll
        for (int kk = 0; kk < 8; kk++) {
            int srcA = (lane & ~3) | (t >> 1);
            int srcB = srcA + 2;
            float u0 = __shfl_sync(0xffffffffu, sc[kk][0], srcA);
            float u1 = __shfl_sync(0xffffffffu, sc[kk][1], srcA);
            float w0 = __shfl_sync(0xffffffffu, sc[kk][2], srcA);
            float w1 = __shfl_sync(0xffffffffu, sc[kk][3], srcA);
            float x0 = __shfl_sync(0xffffffffu, sc[kk][0], srcB);
            float x1 = __shfl_sync(0xffffffffu, sc[kk][1], srcB);
            float y0 = __shfl_sync(0xffffffffu, sc[kk][2], srcB);
            float y1 = __shfl_sync(0xffffffffu, sc[kk][3], srcB);
            bool odd = (t & 1);
            uint32_t A0 = f2tf32(odd ? u1 : u0);
            uint32_t A1 = f2tf32(odd ? w1 : w0);
            uint32_t A2 = f2tf32(odd ? x1 : x0);
            uint32_t A3 = f2tf32(odd ? y1 : y0);
            #pragma unroll
            for (int nt = 0; nt < 8; nt++) {
                uint32_t b0 = Vs[(kk*8+t)*VSD   + nt*8 + g];
                uint32_t b1 = Vs[(kk*8+t+4)*VSD + nt*8 + g];
                mma_tf32(oacc[nt], A0, A1, A2, A3, b0, b1);
            }
        }
        __syncthreads();
    }

    // finalize: quad-reduce l, normalize, write [B,N,H*Dh]
    lA += __shfl_xor_sync(0xffffffffu, lA, 1);
    lA += __shfl_xor_sync(0xffffffffu, lA, 2);
    lB += __shfl_xor_sync(0xffffffffu, lB, 1);
    lB += __shfl_xor_sync(0xffffffffu, lB, 2);
    float iA = 1.f / lA, iB = 1.f / lB;

    float* OA = g_O + ((long)(b*SEQ) + qn + g) * BDIM + h*HD;
    float* OB = OA + 8*BDIM;
    #pragma unroll
    for (int nt = 0; nt < 8; nt++) {
        int c = nt*8 + 2*t;
        float2 va = make_float2(oacc[nt][0]*iA, oacc[nt][1]*iA);
        float2 vb = make_float2(oacc[nt][2]*iB, oacc[nt][3]*iB);
        *(float2*)(OA + c) = va;
        *(float2*)(OB + c) = vb;
    }
}

// ---------------------------------------------------------------------------
extern "C" void kernel_launch(void* const* d_in, const int* in_sizes, int n_in,
                              void* d_out, int out_size)
{
    const float* x      = (const float*)d_in[0];
    const float* qkv_w  = (const float*)d_in[1];
    const float* qkv_b  = (const float*)d_in[2];
    const float* proj_w = (const float*)d_in[3];
    const float* proj_b = (const float*)d_in[4];
    float* out = (float*)d_out;

    dim3 g_qkv(3*BDIM/128, MTOT/128);   // (24, 32)
    gemm_tf32<0><<<g_qkv, 256>>>(x, qkv_w, qkv_b, nullptr, BDIM, 3*BDIM);

    dim3 g_attn(SEQ/128, NH, BB);       // (16, 16, 2)
    attn_tf32<<<g_attn, 256>>>();

    dim3 g_proj(BDIM/128, MTOT/128);    // (8, 32)
    gemm_tf32<1><<<g_proj, 256>>>(nullptr, proj_w, proj_b, out, BDIM, BDIM);
}

// round 6
// speedup vs baseline: 3.5590x; 1.1042x over previous
#include <cuda_runtime.h>
#include <cstdint>

#define BDIM 1024
#define NH 16
#define HD 64
#define BB 2
#define SEQ 2048
#define MTOT (BB*SEQ)
#define QK_SCALE 0.1803368801111204f   // 0.125 * log2(e)

// scratch (device globals — allocation-guard safe).
// NOTE: these symbols must ONLY be referenced from device code; passing them
// as kernel arguments from host code passes the host shadow address (which
// GB300 ATS happily reads as zeros). That was the R4/R5 bug.
__device__ float g_Q[(long)BB*NH*SEQ*HD];
__device__ float g_K[(long)BB*NH*SEQ*HD];
__device__ float g_V[(long)BB*NH*SEQ*HD];
__device__ float g_O[(long)MTOT*BDIM];
__device__ float g_Xr[(long)MTOT*BDIM];        // rna-rounded x
__device__ float g_Wr[(long)3*BDIM*BDIM];      // rna-rounded qkv_w
__device__ float g_PWr[(long)BDIM*BDIM];       // rna-rounded proj_w

// ---------------------------------------------------------------------------
// helpers
// ---------------------------------------------------------------------------
__device__ __forceinline__ uint32_t f2tf32(float f) {
    uint32_t u;
    asm("cvt.rna.tf32.f32 %0, %1;" : "=r"(u) : "f"(f));
    return u;
}
__device__ __forceinline__ float roundtf(float f) {
    return __uint_as_float(f2tf32(f));
}
__device__ __forceinline__ uint32_t smem_u32(const void* p) {
    uint32_t a;
    asm("{ .reg .u64 t; cvta.to.shared.u64 t, %1; cvt.u32.u64 %0, t; }" : "=r"(a) : "l"(p));
    return a;
}
__device__ __forceinline__ void cp16(uint32_t dst, const void* src) {
    asm volatile("cp.async.cg.shared.global [%0], [%1], 16;" :: "r"(dst), "l"(src) : "memory");
}
__device__ __forceinline__ void mma_tf32(float c[4],
                                         uint32_t a0, uint32_t a1, uint32_t a2, uint32_t a3,
                                         uint32_t b0, uint32_t b1) {
    asm volatile(
        "mma.sync.aligned.m16n8k8.row.col.f32.tf32.tf32.f32 "
        "{%0,%1,%2,%3}, {%4,%5,%6,%7}, {%8,%9}, {%0,%1,%2,%3};"
        : "+f"(c[0]), "+f"(c[1]), "+f"(c[2]), "+f"(c[3])
        : "r"(a0), "r"(a1), "r"(a2), "r"(a3), "r"(b0), "r"(b1));
}

// ---------------------------------------------------------------------------
// prepass: rna-round x, qkv_w, proj_w into device copies
// ---------------------------------------------------------------------------
__global__ void round_prep(const float* __restrict__ x, const float* __restrict__ w,
                           const float* __restrict__ pw)
{
    int y = blockIdx.y;
    const float4* src;
    float4* dst;
    long n4;
    if (y == 0)      { src = (const float4*)x;  dst = (float4*)g_Xr;  n4 = (long)MTOT*BDIM/4; }
    else if (y == 1) { src = (const float4*)w;  dst = (float4*)g_Wr;  n4 = (long)3*BDIM*BDIM/4; }
    else             { src = (const float4*)pw; dst = (float4*)g_PWr; n4 = (long)BDIM*BDIM/4; }
    long stride = (long)gridDim.x * blockDim.x;
    for (long i = (long)blockIdx.x*blockDim.x + threadIdx.x; i < n4; i += stride) {
        float4 v = src[i];
        float4 u;
        u.x = roundtf(v.x); u.y = roundtf(v.y);
        u.z = roundtf(v.z); u.w = roundtf(v.w);
        dst[i] = u;
    }
}

// ---------------------------------------------------------------------------
// TF32 GEMM (mma.sync + cp.async 3-stage): C = A @ W^T + bias
// block 128x128, Ktile 16, 256 threads (8 warps 2x4), warp tile 64x32.
// smem stride SA=20 floats (R2-proven conflict-free fragment LDS pattern).
// Operands resolved from device symbols inside the kernel (MODE):
//   MODE 0: A=g_Xr, W=g_Wr,  scatter rna-rounded Q/K/V [B,H,N,Dh]
//   MODE 1: A=g_O,  W=g_PWr, row-major C
// ---------------------------------------------------------------------------
#define SA 20
#define STG_OP (128*SA*4)        // 10240 B per operand per stage
#define STG    (2*STG_OP)        // 20480 B per stage (A+B)
#define NST    3

template<int MODE>
__global__ __launch_bounds__(256, 2)
void gemm_tc(const float* __restrict__ bias, float* __restrict__ Cout,
             int K, int Nout)
{
    extern __shared__ char smem[];
    uint32_t sbase = smem_u32(smem);
    const float* Ab = (MODE == 1) ? (const float*)g_O  : (const float*)g_Xr;
    const float* Wb = (MODE == 1) ? (const float*)g_PWr : (const float*)g_Wr;

    int tid = threadIdx.x, warp = tid >> 5, lane = tid & 31;
    int g = lane >> 2, t = lane & 3;
    int wm = (warp >> 2) * 64, wn = (warp & 3) * 32;
    int m0 = blockIdx.y * 128, n0 = blockIdx.x * 128;

    // cp.async mapping: 2 A-chunks + 2 B-chunks (16B) per thread per stage
    const float* asrc[2];
    const float* bsrc[2];
    uint32_t doff[2];
    #pragma unroll
    for (int i = 0; i < 2; i++) {
        int cid = i*256 + tid;          // 0..511
        int row = cid >> 2, ch = cid & 3;
        doff[i] = (uint32_t)(row*SA*4 + ch*16);
        asrc[i] = Ab + (long)(m0 + row)*K + ch*4;
        bsrc[i] = Wb + (long)(n0 + row)*K + ch*4;
    }

    float acc[4][4][4];
    #pragma unroll
    for (int i = 0; i < 4; i++)
        #pragma unroll
        for (int j = 0; j < 4; j++)
            #pragma unroll
            for (int c = 0; c < 4; c++) acc[i][j][c] = 0.f;

    int niter = K >> 4;

    // prologue: stages 0,1
    #pragma unroll
    for (int s = 0; s < 2; s++) {
        uint32_t db = sbase + s*STG;
        #pragma unroll
        for (int i = 0; i < 2; i++) {
            cp16(db + doff[i],          asrc[i] + s*16);
            cp16(db + STG_OP + doff[i], bsrc[i] + s*16);
        }
        asm volatile("cp.async.commit_group;" ::: "memory");
    }

    for (int it = 0; it < niter; ++it) {
        asm volatile("cp.async.wait_group 1;" ::: "memory");
        __syncthreads();

        int nx = it + 2;
        if (nx < niter) {
            uint32_t db = sbase + (nx % NST)*STG;
            long koff = (long)nx * 16;
            #pragma unroll
            for (int i = 0; i < 2; i++) {
                cp16(db + doff[i],          asrc[i] + koff);
                cp16(db + STG_OP + doff[i], bsrc[i] + koff);
            }
        }
        asm volatile("cp.async.commit_group;" ::: "memory");

        const uint32_t* as = (const uint32_t*)(smem + (it % NST)*STG);
        const uint32_t* bs = (const uint32_t*)(smem + (it % NST)*STG + STG_OP);

        #pragma unroll
        for (int kk = 0; kk < 16; kk += 8) {
            uint32_t af[4][4], bf[4][2];
            #pragma unroll
            for (int mt = 0; mt < 4; mt++) {
                int rw = wm + mt*16;
                af[mt][0] = as[(rw+g)*SA   + kk + t];
                af[mt][1] = as[(rw+g+8)*SA + kk + t];
                af[mt][2] = as[(rw+g)*SA   + kk + t + 4];
                af[mt][3] = as[(rw+g+8)*SA + kk + t + 4];
            }
            #pragma unroll
            for (int nt = 0; nt < 4; nt++) {
                int cw = wn + nt*8 + g;
                bf[nt][0] = bs[cw*SA + kk + t];
                bf[nt][1] = bs[cw*SA + kk + t + 4];
            }
            #pragma unroll
            for (int mt = 0; mt < 4; mt++)
                #pragma unroll
                for (int nt = 0; nt < 4; nt++)
                    mma_tf32(acc[mt][nt], af[mt][0], af[mt][1], af[mt][2], af[mt][3],
                             bf[nt][0], bf[nt][1]);
        }
    }

    // epilogue (MODE0 stores rna-rounded so downstream tf32 sees exact values)
    #pragma unroll
    for (int mt = 0; mt < 4; mt++) {
        int rowA = m0 + wm + mt*16 + g;
        int rowB = rowA + 8;
        #pragma unroll
        for (int nt = 0; nt < 4; nt++) {
            int col = n0 + wn + nt*8 + 2*t;
            float b0v = bias[col], b1v = bias[col+1];
            float2 va = make_float2(acc[mt][nt][0] + b0v, acc[mt][nt][1] + b1v);
            float2 vb = make_float2(acc[mt][nt][2] + b0v, acc[mt][nt][3] + b1v);
            if (MODE == 0) {
                va.x = roundtf(va.x); va.y = roundtf(va.y);
                vb.x = roundtf(vb.x); vb.y = roundtf(vb.y);
                int which = col >> 10;
                int c = col & (BDIM - 1);
                int hh = c >> 6, d = c & 63;
                float* dst = (which == 0) ? g_Q : (which == 1) ? g_K : g_V;
                {
                    int b = rowA >> 11, n = rowA & (SEQ - 1);
                    *(float2*)(dst + ((((long)b*NH + hh)*SEQ) + n)*HD + d) = va;
                }
                {
                    int b = rowB >> 11, n = rowB & (SEQ - 1);
                    *(float2*)(dst + ((((long)b*NH + hh)*SEQ) + n)*HD + d) = vb;
                }
            } else {
                *(float2*)(Cout + (long)rowA * Nout + col) = va;
                *(float2*)(Cout + (long)rowB * Nout + col) = vb;
            }
        }
    }
}

// ---------------------------------------------------------------------------
// TF32 flash attention (mma.sync) — R2-proven structure. K/V pre-rounded so
// staging is a plain float4 copy. Direct LDS.32 fragment reads (KSD=68,
// VSD=72 conflict-free). Output written rna-rounded to g_O.
// ---------------------------------------------------------------------------
#define KSD 68
#define VSD 72
__global__ __launch_bounds__(256)
void attn_tf32()
{
    __shared__ __align__(16) float Ks[64*KSD];
    __shared__ __align__(16) float Vs[64*VSD];

    int tid  = threadIdx.x;
    int lane = tid & 31, warp = tid >> 5;
    int g = lane >> 2, t = lane & 3;
    int b = blockIdx.z, h = blockIdx.y;
    long base = ((long)(b*NH + h)) * SEQ * HD;
    const float* Qb = g_Q + base;
    const float* Kb = g_K + base;
    const float* Vb = g_V + base;

    int qn = blockIdx.x * 128 + warp * 16;

    // Q fragments in registers (scaled then rna-rounded)
    uint32_t qf[8][4];
    {
        const float* q0 = Qb + (long)(qn + g) * HD;
        const float* q1 = Qb + (long)(qn + g + 8) * HD;
        #pragma unroll
        for (int kk = 0; kk < 8; kk++) {
            int c = kk*8 + t;
            qf[kk][0] = f2tf32(q0[c]   * QK_SCALE);
            qf[kk][1] = f2tf32(q1[c]   * QK_SCALE);
            qf[kk][2] = f2tf32(q0[c+4] * QK_SCALE);
            qf[kk][3] = f2tf32(q1[c+4] * QK_SCALE);
        }
    }

    float oacc[8][4];
    #pragma unroll
    for (int i = 0; i < 8; i++)
        #pragma unroll
        for (int j = 0; j < 4; j++) oacc[i][j] = 0.f;
    float mA = -1e30f, mB = -1e30f, lA = 0.f, lB = 0.f;

    float4 rk[4], rv[4];
    {
        const float4* ks = (const float4*)Kb;
        const float4* vs = (const float4*)Vb;
        #pragma unroll
        for (int i = 0; i < 4; i++) { rk[i] = ks[tid + i*256]; rv[i] = vs[tid + i*256]; }
    }

    for (int kt = 0; kt < SEQ/64; ++kt) {
        #pragma unroll
        for (int i = 0; i < 4; i++) {
            int id = tid + i*256;
            int row = id >> 4, c4 = (id & 15) * 4;
            *(float4*)(Ks + row*KSD + c4) = rk[i];
            *(float4*)(Vs + row*VSD + c4) = rv[i];
        }
        __syncthreads();

        if (kt + 1 < SEQ/64) {
            const float4* ks = (const float4*)(Kb + (long)(kt+1)*64*HD);
            const float4* vs = (const float4*)(Vb + (long)(kt+1)*64*HD);
            #pragma unroll
            for (int i = 0; i < 4; i++) { rk[i] = ks[tid + i*256]; rv[i] = vs[tid + i*256]; }
        }

        // S = Q @ K^T  (log2 units)
        float sc[8][4];
        #pragma unroll
        for (int i = 0; i < 8; i++)
            #pragma unroll
            for (int j = 0; j < 4; j++) sc[i][j] = 0.f;
        #pragma unroll
        for (int kk = 0; kk < 8; kk++) {
            #pragma unroll
            for (int nt = 0; nt < 8; nt++) {
                uint32_t b0 = __float_as_uint(Ks[(nt*8+g)*KSD + kk*8 + t]);
                uint32_t b1 = __float_as_uint(Ks[(nt*8+g)*KSD + kk*8 + t + 4]);
                mma_tf32(sc[nt], qf[kk][0], qf[kk][1], qf[kk][2], qf[kk][3], b0, b1);
            }
        }

        // online softmax (rows g / g+8, per-quad stats)
        float mlA = -1e30f, mlB = -1e30f;
        #pragma unroll
        for (int nt = 0; nt < 8; nt++) {
            mlA = fmaxf(mlA, fmaxf(sc[nt][0], sc[nt][1]));
            mlB = fmaxf(mlB, fmaxf(sc[nt][2], sc[nt][3]));
        }
        mlA = fmaxf(mlA, __shfl_xor_sync(0xffffffffu, mlA, 1));
        mlA = fmaxf(mlA, __shfl_xor_sync(0xffffffffu, mlA, 2));
        mlB = fmaxf(mlB, __shfl_xor_sync(0xffffffffu, mlB, 1));
        mlB = fmaxf(mlB, __shfl_xor_sync(0xffffffffu, mlB, 2));
        float mnA = fmaxf(mA, mlA), mnB = fmaxf(mB, mlB);
        float cA = exp2f(mA - mnA), cB = exp2f(mB - mnB);
        lA *= cA; lB *= cB;
        #pragma unroll
        for (int nt = 0; nt < 8; nt++) {
            oacc[nt][0] *= cA; oacc[nt][1] *= cA;
            oacc[nt][2] *= cB; oacc[nt][3] *= cB;
        }
        #pragma unroll
        for (int nt = 0; nt < 8; nt++) {
            float p0 = exp2f(sc[nt][0] - mnA);
            float p1 = exp2f(sc[nt][1] - mnA);
            float p2 = exp2f(sc[nt][2] - mnB);
            float p3 = exp2f(sc[nt][3] - mnB);
            lA += p0 + p1; lB += p2 + p3;
            sc[nt][0] = p0; sc[nt][1] = p1; sc[nt][2] = p2; sc[nt][3] = p3;
        }
        mA = mnA; mB = mnB;

        // O += P @ V ; P C-frag -> A-frag via quad shuffles
        #pragma unroll
        for (int kk = 0; kk < 8; kk++) {
            int srcA = (lane & ~3) | (t >> 1);
            int srcB = srcA + 2;
            float u0 = __shfl_sync(0xffffffffu, sc[kk][0], srcA);
            float u1 = __shfl_sync(0xffffffffu, sc[kk][1], srcA);
            float w0 = __shfl_sync(0xffffffffu, sc[kk][2], srcA);
            float w1 = __shfl_sync(0xffffffffu, sc[kk][3], srcA);
            float x0 = __shfl_sync(0xffffffffu, sc[kk][0], srcB);
            float x1 = __shfl_sync(0xffffffffu, sc[kk][1], srcB);
            float y0 = __shfl_sync(0xffffffffu, sc[kk][2], srcB);
            float y1 = __shfl_sync(0xffffffffu, sc[kk][3], srcB);
            bool odd = (t & 1);
            uint32_t A0 = f2tf32(odd ? u1 : u0);
            uint32_t A1 = f2tf32(odd ? w1 : w0);
            uint32_t A2 = f2tf32(odd ? x1 : x0);
            uint32_t A3 = f2tf32(odd ? y1 : y0);
            #pragma unroll
            for (int nt = 0; nt < 8; nt++) {
                uint32_t b0 = __float_as_uint(Vs[(kk*8+t)*VSD   + nt*8 + g]);
                uint32_t b1 = __float_as_uint(Vs[(kk*8+t+4)*VSD + nt*8 + g]);
                mma_tf32(oacc[nt], A0, A1, A2, A3, b0, b1);
            }
        }
        __syncthreads();
    }

    lA += __shfl_xor_sync(0xffffffffu, lA, 1);
    lA += __shfl_xor_sync(0xffffffffu, lA, 2);
    lB += __shfl_xor_sync(0xffffffffu, lB, 1);
    lB += __shfl_xor_sync(0xffffffffu, lB, 2);
    float iA = 1.f / lA, iB = 1.f / lB;

    float* OA = g_O + ((long)(b*SEQ) + qn + g) * BDIM + h*HD;
    float* OB = OA + 8*BDIM;
    #pragma unroll
    for (int nt = 0; nt < 8; nt++) {
        int c = nt*8 + 2*t;
        float2 va = make_float2(roundtf(oacc[nt][0]*iA), roundtf(oacc[nt][1]*iA));
        float2 vb = make_float2(roundtf(oacc[nt][2]*iB), roundtf(oacc[nt][3]*iB));
        *(float2*)(OA + c) = va;
        *(float2*)(OB + c) = vb;
    }
}

// ---------------------------------------------------------------------------
extern "C" void kernel_launch(void* const* d_in, const int* in_sizes, int n_in,
                              void* d_out, int out_size)
{
    const float* x      = (const float*)d_in[0];
    const float* qkv_w  = (const float*)d_in[1];
    const float* qkv_b  = (const float*)d_in[2];
    const float* proj_w = (const float*)d_in[3];
    const float* proj_b = (const float*)d_in[4];
    float* out = (float*)d_out;

    int shmem = NST * STG;   // 61440
    cudaFuncSetAttribute(gemm_tc<0>, cudaFuncAttributeMaxDynamicSharedMemorySize, shmem);
    cudaFuncSetAttribute(gemm_tc<1>, cudaFuncAttributeMaxDynamicSharedMemorySize, shmem);

    round_prep<<<dim3(1024, 3), 256>>>(x, qkv_w, proj_w);

    dim3 g_qkv(3*BDIM/128, MTOT/128);   // (24, 32)
    gemm_tc<0><<<g_qkv, 256, shmem>>>(qkv_b, nullptr, BDIM, 3*BDIM);

    dim3 g_attn(SEQ/128, NH, BB);       // (16, 16, 2)
    attn_tf32<<<g_attn, 256>>>();

    dim3 g_proj(BDIM/128, MTOT/128);    // (8, 32)
    gemm_tc<1><<<g_proj, 256, shmem>>>(proj_b, out, BDIM, BDIM);
}

// round 7
// speedup vs baseline: 3.6032x; 1.0124x over previous
#include <cuda_runtime.h>
#include <cstdint>

#define BDIM 1024
#define NH 16
#define HD 64
#define BB 2
#define SEQ 2048
#define MTOT (BB*SEQ)
#define QK_SCALE 0.1803368801111204f   // 0.125 * log2(e)

// scratch (device globals — allocation-guard safe). Referenced ONLY from
// device code (host-passing gives host shadow addrs — the R4/R5 bug).
__device__ float g_Q[(long)BB*NH*SEQ*HD];
__device__ float g_K[(long)BB*NH*SEQ*HD];
__device__ float g_V[(long)BB*NH*SEQ*HD];
__device__ float g_O[(long)MTOT*BDIM];
__device__ float g_Xr[(long)MTOT*BDIM];
__device__ float g_Wr[(long)3*BDIM*BDIM];
__device__ float g_PWr[(long)BDIM*BDIM];

// ---------------------------------------------------------------------------
// helpers
// ---------------------------------------------------------------------------
__device__ __forceinline__ uint32_t f2tf32(float f) {
    uint32_t u;
    asm("cvt.rna.tf32.f32 %0, %1;" : "=r"(u) : "f"(f));
    return u;
}
__device__ __forceinline__ float roundtf(float f) {
    return __uint_as_float(f2tf32(f));
}
__device__ __forceinline__ float ex2f(float x) {
    float y;
    asm("ex2.approx.ftz.f32 %0, %1;" : "=f"(y) : "f"(x));
    return y;
}
__device__ __forceinline__ uint32_t smem_u32(const void* p) {
    uint32_t a;
    asm("{ .reg .u64 t; cvta.to.shared.u64 t, %1; cvt.u32.u64 %0, t; }" : "=r"(a) : "l"(p));
    return a;
}
__device__ __forceinline__ void cp16(uint32_t dst, const void* src) {
    asm volatile("cp.async.cg.shared.global [%0], [%1], 16;" :: "r"(dst), "l"(src) : "memory");
}
__device__ __forceinline__ void mma_tf32(float c[4],
                                         uint32_t a0, uint32_t a1, uint32_t a2, uint32_t a3,
                                         uint32_t b0, uint32_t b1) {
    asm volatile(
        "mma.sync.aligned.m16n8k8.row.col.f32.tf32.tf32.f32 "
        "{%0,%1,%2,%3}, {%4,%5,%6,%7}, {%8,%9}, {%0,%1,%2,%3};"
        : "+f"(c[0]), "+f"(c[1]), "+f"(c[2]), "+f"(c[3])
        : "r"(a0), "r"(a1), "r"(a2), "r"(a3), "r"(b0), "r"(b1));
}

// ---------------------------------------------------------------------------
// prepass: rna-round x, qkv_w, proj_w into device copies
// ---------------------------------------------------------------------------
__global__ void round_prep(const float* __restrict__ x, const float* __restrict__ w,
                           const float* __restrict__ pw)
{
    int y = blockIdx.y;
    const float4* src;
    float4* dst;
    long n4;
    if (y == 0)      { src = (const float4*)x;  dst = (float4*)g_Xr;  n4 = (long)MTOT*BDIM/4; }
    else if (y == 1) { src = (const float4*)w;  dst = (float4*)g_Wr;  n4 = (long)3*BDIM*BDIM/4; }
    else             { src = (const float4*)pw; dst = (float4*)g_PWr; n4 = (long)BDIM*BDIM/4; }
    long stride = (long)gridDim.x * blockDim.x;
    for (long i = (long)blockIdx.x*blockDim.x + threadIdx.x; i < n4; i += stride) {
        float4 v = src[i];
        float4 u;
        u.x = roundtf(v.x); u.y = roundtf(v.y);
        u.z = roundtf(v.z); u.w = roundtf(v.w);
        dst[i] = u;
    }
}

// ---------------------------------------------------------------------------
// TF32 GEMM (mma.sync + cp.async 3-stage) — unchanged from R6 (proven).
// ---------------------------------------------------------------------------
#define SA 20
#define STG_OP (128*SA*4)
#define STG    (2*STG_OP)
#define NST    3

template<int MODE>
__global__ __launch_bounds__(256, 2)
void gemm_tc(const float* __restrict__ bias, float* __restrict__ Cout,
             int K, int Nout)
{
    extern __shared__ char smem[];
    uint32_t sbase = smem_u32(smem);
    const float* Ab = (MODE == 1) ? (const float*)g_O  : (const float*)g_Xr;
    const float* Wb = (MODE == 1) ? (const float*)g_PWr : (const float*)g_Wr;

    int tid = threadIdx.x, warp = tid >> 5, lane = tid & 31;
    int g = lane >> 2, t = lane & 3;
    int wm = (warp >> 2) * 64, wn = (warp & 3) * 32;
    int m0 = blockIdx.y * 128, n0 = blockIdx.x * 128;

    const float* asrc[2];
    const float* bsrc[2];
    uint32_t doff[2];
    #pragma unroll
    for (int i = 0; i < 2; i++) {
        int cid = i*256 + tid;
        int row = cid >> 2, ch = cid & 3;
        doff[i] = (uint32_t)(row*SA*4 + ch*16);
        asrc[i] = Ab + (long)(m0 + row)*K + ch*4;
        bsrc[i] = Wb + (long)(n0 + row)*K + ch*4;
    }

    float acc[4][4][4];
    #pragma unroll
    for (int i = 0; i < 4; i++)
        #pragma unroll
        for (int j = 0; j < 4; j++)
            #pragma unroll
            for (int c = 0; c < 4; c++) acc[i][j][c] = 0.f;

    int niter = K >> 4;

    #pragma unroll
    for (int s = 0; s < 2; s++) {
        uint32_t db = sbase + s*STG;
        #pragma unroll
        for (int i = 0; i < 2; i++) {
            cp16(db + doff[i],          asrc[i] + s*16);
            cp16(db + STG_OP + doff[i], bsrc[i] + s*16);
        }
        asm volatile("cp.async.commit_group;" ::: "memory");
    }

    for (int it = 0; it < niter; ++it) {
        asm volatile("cp.async.wait_group 1;" ::: "memory");
        __syncthreads();

        int nx = it + 2;
        if (nx < niter) {
            uint32_t db = sbase + (nx % NST)*STG;
            long koff = (long)nx * 16;
            #pragma unroll
            for (int i = 0; i < 2; i++) {
                cp16(db + doff[i],          asrc[i] + koff);
                cp16(db + STG_OP + doff[i], bsrc[i] + koff);
            }
        }
        asm volatile("cp.async.commit_group;" ::: "memory");

        const uint32_t* as = (const uint32_t*)(smem + (it % NST)*STG);
        const uint32_t* bs = (const uint32_t*)(smem + (it % NST)*STG + STG_OP);

        #pragma unroll
        for (int kk = 0; kk < 16; kk += 8) {
            uint32_t af[4][4], bf[4][2];
            #pragma unroll
            for (int mt = 0; mt < 4; mt++) {
                int rw = wm + mt*16;
                af[mt][0] = as[(rw+g)*SA   + kk + t];
                af[mt][1] = as[(rw+g+8)*SA + kk + t];
                af[mt][2] = as[(rw+g)*SA   + kk + t + 4];
                af[mt][3] = as[(rw+g+8)*SA + kk + t + 4];
            }
            #pragma unroll
            for (int nt = 0; nt < 4; nt++) {
                int cw = wn + nt*8 + g;
                bf[nt][0] = bs[cw*SA + kk + t];
                bf[nt][1] = bs[cw*SA + kk + t + 4];
            }
            #pragma unroll
            for (int mt = 0; mt < 4; mt++)
                #pragma unroll
                for (int nt = 0; nt < 4; nt++)
                    mma_tf32(acc[mt][nt], af[mt][0], af[mt][1], af[mt][2], af[mt][3],
                             bf[nt][0], bf[nt][1]);
        }
    }

    #pragma unroll
    for (int mt = 0; mt < 4; mt++) {
        int rowA = m0 + wm + mt*16 + g;
        int rowB = rowA + 8;
        #pragma unroll
        for (int nt = 0; nt < 4; nt++) {
            int col = n0 + wn + nt*8 + 2*t;
            float b0v = bias[col], b1v = bias[col+1];
            float2 va = make_float2(acc[mt][nt][0] + b0v, acc[mt][nt][1] + b1v);
            float2 vb = make_float2(acc[mt][nt][2] + b0v, acc[mt][nt][3] + b1v);
            if (MODE == 0) {
                va.x = roundtf(va.x); va.y = roundtf(va.y);
                vb.x = roundtf(vb.x); vb.y = roundtf(vb.y);
                int which = col >> 10;
                int c = col & (BDIM - 1);
                int hh = c >> 6, d = c & 63;
                float* dst = (which == 0) ? g_Q : (which == 1) ? g_K : g_V;
                {
                    int b = rowA >> 11, n = rowA & (SEQ - 1);
                    *(float2*)(dst + ((((long)b*NH + hh)*SEQ) + n)*HD + d) = va;
                }
                {
                    int b = rowB >> 11, n = rowB & (SEQ - 1);
                    *(float2*)(dst + ((((long)b*NH + hh)*SEQ) + n)*HD + d) = vb;
                }
            } else {
                *(float2*)(Cout + (long)rowA * Nout + col) = va;
                *(float2*)(Cout + (long)rowB * Nout + col) = vb;
            }
        }
    }
}

// ---------------------------------------------------------------------------
// TF32 flash attention v2: 4 warps x 32 q-rows (two 16-row m-tiles per warp),
// so K/V fragment LDS is amortized over 2x the MMAs (crossbar traffic halved).
// cp.async 3-stage K/V staging, one barrier per tile. All fragment layout
// math identical to the R2/R6-proven kernel; just an added mt dimension.
// ---------------------------------------------------------------------------
#define KSD 68
#define VSD 72
#define KBY (64*KSD*4)            // 17408
#define ABUF (KBY + 64*VSD*4)     // 35840
#define ANST 3

__global__ __launch_bounds__(128, 2)
void attn_tf32()
{
    extern __shared__ __align__(16) char dsm[];

    int tid  = threadIdx.x;
    int lane = tid & 31, warp = tid >> 5;      // warp 0..3
    int g = lane >> 2, t = lane & 3;
    int b = blockIdx.z, h = blockIdx.y;
    long base = ((long)(b*NH + h)) * SEQ * HD;
    const float* Qb = g_Q + base;
    const float* Kb = g_K + base;
    const float* Vb = g_V + base;

    int qn = blockIdx.x * 128 + warp * 32;

    // cp.async staging: thread -> row tid>>1 (0..63), chunk half (tid&1)*8
    uint32_t sb = smem_u32(dsm);
    int sr = tid >> 1;
    int sc0 = (tid & 1) * 8;
    uint32_t kdst = sb + (uint32_t)(sr*KSD*4 + sc0*16);
    uint32_t vdst = sb + KBY + (uint32_t)(sr*VSD*4 + sc0*16);
    const float* ksrc = Kb + (long)sr*HD + sc0*4;
    const float* vsrc = Vb + (long)sr*HD + sc0*4;

    // Q fragments (scaled, rna-rounded) for both m-tiles
    uint32_t qf[8][2][4];
    #pragma unroll
    for (int mt = 0; mt < 2; mt++) {
        const float* q0 = Qb + (long)(qn + mt*16 + g) * HD;
        const float* q1 = q0 + 8*HD;
        #pragma unroll
        for (int kk = 0; kk < 8; kk++) {
            int c = kk*8 + t;
            qf[kk][mt][0] = f2tf32(q0[c]   * QK_SCALE);
            qf[kk][mt][1] = f2tf32(q1[c]   * QK_SCALE);
            qf[kk][mt][2] = f2tf32(q0[c+4] * QK_SCALE);
            qf[kk][mt][3] = f2tf32(q1[c+4] * QK_SCALE);
        }
    }

    float oacc[2][8][4];
    #pragma unroll
    for (int mt = 0; mt < 2; mt++)
        #pragma unroll
        for (int i = 0; i < 8; i++)
            #pragma unroll
            for (int j = 0; j < 4; j++) oacc[mt][i][j] = 0.f;
    float mA[2] = {-1e30f, -1e30f}, mB[2] = {-1e30f, -1e30f};
    float lA[2] = {0.f, 0.f},       lB[2] = {0.f, 0.f};

    // prologue: stages 0,1
    #pragma unroll
    for (int s = 0; s < 2; s++) {
        uint32_t so = (uint32_t)s * ABUF;
        long go = (long)s * 64 * HD;
        #pragma unroll
        for (int j = 0; j < 8; j++) {
            cp16(kdst + so + j*16, ksrc + go + j*4);
            cp16(vdst + so + j*16, vsrc + go + j*4);
        }
        asm volatile("cp.async.commit_group;" ::: "memory");
    }

    const int NT = SEQ/64;
    for (int kt = 0; kt < NT; ++kt) {
        asm volatile("cp.async.wait_group 1;" ::: "memory");
        __syncthreads();   // all of tile kt visible; all warps done with buf (kt+2)%3

        // issue stage kt+2 (post-barrier: safe w.r.t. readers of buf (kt+2)%3)
        if (kt + 2 < NT) {
            uint32_t so = (uint32_t)((kt+2) % ANST) * ABUF;
            long go = (long)(kt+2) * 64 * HD;
            #pragma unroll
            for (int j = 0; j < 8; j++) {
                cp16(kdst + so + j*16, ksrc + go + j*4);
                cp16(vdst + so + j*16, vsrc + go + j*4);
            }
        }
        asm volatile("cp.async.commit_group;" ::: "memory");

        const float* Ks = (const float*)(dsm + (kt % ANST)*ABUF);
        const float* Vs = (const float*)(dsm + (kt % ANST)*ABUF + KBY);

        // S = Q @ K^T (log2 units) — K frag LDS shared across both m-tiles
        float sc[2][8][4];
        #pragma unroll
        for (int mt = 0; mt < 2; mt++)
            #pragma unroll
            for (int i = 0; i < 8; i++)
                #pragma unroll
                for (int j = 0; j < 4; j++) sc[mt][i][j] = 0.f;
        #pragma unroll
        for (int kk = 0; kk < 8; kk++) {
            #pragma unroll
            for (int nt = 0; nt < 8; nt++) {
                uint32_t b0 = __float_as_uint(Ks[(nt*8+g)*KSD + kk*8 + t]);
                uint32_t b1 = __float_as_uint(Ks[(nt*8+g)*KSD + kk*8 + t + 4]);
                mma_tf32(sc[0][nt], qf[kk][0][0], qf[kk][0][1], qf[kk][0][2], qf[kk][0][3], b0, b1);
                mma_tf32(sc[1][nt], qf[kk][1][0], qf[kk][1][1], qf[kk][1][2], qf[kk][1][3], b0, b1);
            }
        }

        // online softmax per m-tile
        #pragma unroll
        for (int mt = 0; mt < 2; mt++) {
            float mlA = -1e30f, mlB = -1e30f;
            #pragma unroll
            for (int nt = 0; nt < 8; nt++) {
                mlA = fmaxf(mlA, fmaxf(sc[mt][nt][0], sc[mt][nt][1]));
                mlB = fmaxf(mlB, fmaxf(sc[mt][nt][2], sc[mt][nt][3]));
            }
            mlA = fmaxf(mlA, __shfl_xor_sync(0xffffffffu, mlA, 1));
            mlA = fmaxf(mlA, __shfl_xor_sync(0xffffffffu, mlA, 2));
            mlB = fmaxf(mlB, __shfl_xor_sync(0xffffffffu, mlB, 1));
            mlB = fmaxf(mlB, __shfl_xor_sync(0xffffffffu, mlB, 2));
            float mnA = fmaxf(mA[mt], mlA), mnB = fmaxf(mB[mt], mlB);
            float cA = ex2f(mA[mt] - mnA), cB = ex2f(mB[mt] - mnB);
            lA[mt] *= cA; lB[mt] *= cB;
            #pragma unroll
            for (int nt = 0; nt < 8; nt++) {
                oacc[mt][nt][0] *= cA; oacc[mt][nt][1] *= cA;
                oacc[mt][nt][2] *= cB; oacc[mt][nt][3] *= cB;
            }
            #pragma unroll
            for (int nt = 0; nt < 8; nt++) {
                float p0 = ex2f(sc[mt][nt][0] - mnA);
                float p1 = ex2f(sc[mt][nt][1] - mnA);
                float p2 = ex2f(sc[mt][nt][2] - mnB);
                float p3 = ex2f(sc[mt][nt][3] - mnB);
                lA[mt] += p0 + p1; lB[mt] += p2 + p3;
                sc[mt][nt][0] = p0; sc[mt][nt][1] = p1;
                sc[mt][nt][2] = p2; sc[mt][nt][3] = p3;
            }
            mA[mt] = mnA; mB[mt] = mnB;
        }

        // O += P @ V ; P C-frag -> A-frag via quad shuffles; V LDS shared
        int srcA = (lane & ~3) | (t >> 1);
        int srcB = srcA + 2;
        bool odd = (t & 1);
        #pragma unroll
        for (int kk = 0; kk < 8; kk++) {
            uint32_t Af[2][4];
            #pragma unroll
            for (int mt = 0; mt < 2; mt++) {
                float u0 = __shfl_sync(0xffffffffu, sc[mt][kk][0], srcA);
                float u1 = __shfl_sync(0xffffffffu, sc[mt][kk][1], srcA);
                float w0 = __shfl_sync(0xffffffffu, sc[mt][kk][2], srcA);
                float w1 = __shfl_sync(0xffffffffu, sc[mt][kk][3], srcA);
                float x0 = __shfl_sync(0xffffffffu, sc[mt][kk][0], srcB);
                float x1 = __shfl_sync(0xffffffffu, sc[mt][kk][1], srcB);
                float y0 = __shfl_sync(0xffffffffu, sc[mt][kk][2], srcB);
                float y1 = __shfl_sync(0xffffffffu, sc[mt][kk][3], srcB);
                Af[mt][0] = f2tf32(odd ? u1 : u0);
                Af[mt][1] = f2tf32(odd ? w1 : w0);
                Af[mt][2] = f2tf32(odd ? x1 : x0);
                Af[mt][3] = f2tf32(odd ? y1 : y0);
            }
            #pragma unroll
            for (int nt = 0; nt < 8; nt++) {
                uint32_t b0 = __float_as_uint(Vs[(kk*8+t)*VSD   + nt*8 + g]);
                uint32_t b1 = __float_as_uint(Vs[(kk*8+t+4)*VSD + nt*8 + g]);
                mma_tf32(oacc[0][nt], Af[0][0], Af[0][1], Af[0][2], Af[0][3], b0, b1);
                mma_tf32(oacc[1][nt], Af[1][0], Af[1][1], Af[1][2], Af[1][3], b0, b1);
            }
        }
    }

    // finalize per m-tile
    #pragma unroll
    for (int mt = 0; mt < 2; mt++) {
        float la = lA[mt], lb = lB[mt];
        la += __shfl_xor_sync(0xffffffffu, la, 1);
        la += __shfl_xor_sync(0xffffffffu, la, 2);
        lb += __shfl_xor_sync(0xffffffffu, lb, 1);
        lb += __shfl_xor_sync(0xffffffffu, lb, 2);
        float iA = 1.f / la, iB = 1.f / lb;

        float* OA = g_O + ((long)(b*SEQ) + qn + mt*16 + g) * BDIM + h*HD;
        float* OB = OA + 8*BDIM;
        #pragma unroll
        for (int nt = 0; nt < 8; nt++) {
            int c = nt*8 + 2*t;
            float2 va = make_float2(roundtf(oacc[mt][nt][0]*iA), roundtf(oacc[mt][nt][1]*iA));
            float2 vb = make_float2(roundtf(oacc[mt][nt][2]*iB), roundtf(oacc[mt][nt][3]*iB));
            *(float2*)(OA + c) = va;
            *(float2*)(OB + c) = vb;
        }
    }
}

// ---------------------------------------------------------------------------
extern "C" void kernel_launch(void* const* d_in, const int* in_sizes, int n_in,
                              void* d_out, int out_size)
{
    const float* x      = (const float*)d_in[0];
    const float* qkv_w  = (const float*)d_in[1];
    const float* qkv_b  = (const float*)d_in[2];
    const float* proj_w = (const float*)d_in[3];
    const float* proj_b = (const float*)d_in[4];
    float* out = (float*)d_out;

    int shmem = NST * STG;           // 61440
    int ashmem = ANST * ABUF;        // 107520
    cudaFuncSetAttribute(gemm_tc<0>, cudaFuncAttributeMaxDynamicSharedMemorySize, shmem);
    cudaFuncSetAttribute(gemm_tc<1>, cudaFuncAttributeMaxDynamicSharedMemorySize, shmem);
    cudaFuncSetAttribute(attn_tf32, cudaFuncAttributeMaxDynamicSharedMemorySize, ashmem);

    round_prep<<<dim3(1024, 3), 256>>>(x, qkv_w, proj_w);

    dim3 g_qkv(3*BDIM/128, MTOT/128);   // (24, 32)
    gemm_tc<0><<<g_qkv, 256, shmem>>>(qkv_b, nullptr, BDIM, 3*BDIM);

    dim3 g_attn(SEQ/128, NH, BB);       // (16, 16, 2)
    attn_tf32<<<g_attn, 128, ashmem>>>();

    dim3 g_proj(BDIM/128, MTOT/128);    // (8, 32)
    gemm_tc<1><<<g_proj, 256, shmem>>>(proj_b, out, BDIM, BDIM);
}

// round 8
// speedup vs baseline: 7.9606x; 2.2093x over previous
#include <cuda_runtime.h>
#include <cuda_fp16.h>
#include <cstdint>

#define BDIM 1024
#define NH 16
#define HD 64
#define BB 2
#define SEQ 2048
#define MTOT (BB*SEQ)
#define QK_SCALE 0.1803368801111204f   // 0.125 * log2(e)

// scratch (device globals — allocation-guard safe). Referenced ONLY from
// device code (host-passing gives host shadow addrs — the R4/R5 bug).
__device__ __half g_Q [(long)BB*NH*SEQ*HD];     // Q pre-scaled by QK_SCALE
__device__ __half g_K [(long)BB*NH*SEQ*HD];
__device__ __half g_Vt[(long)BB*NH*HD*SEQ];     // V transposed: [b,h,d,n]
__device__ __half g_O [(long)MTOT*BDIM];        // attention out, head-concat
__device__ __half g_Xh[(long)MTOT*BDIM];
__device__ __half g_Wh[(long)3*BDIM*BDIM];
__device__ __half g_PWh[(long)BDIM*BDIM];

// ---------------------------------------------------------------------------
// helpers
// ---------------------------------------------------------------------------
__device__ __forceinline__ float ex2f(float x) {
    float y;
    asm("ex2.approx.ftz.f32 %0, %1;" : "=f"(y) : "f"(x));
    return y;
}
__device__ __forceinline__ uint32_t smem_u32(const void* p) {
    uint32_t a;
    asm("{ .reg .u64 t; cvta.to.shared.u64 t, %1; cvt.u32.u64 %0, t; }" : "=r"(a) : "l"(p));
    return a;
}
__device__ __forceinline__ void cp16(uint32_t dst, const void* src) {
    asm volatile("cp.async.cg.shared.global [%0], [%1], 16;" :: "r"(dst), "l"(src) : "memory");
}
__device__ __forceinline__ uint32_t packh2(float lo, float hi) {
    __half2 h = __floats2half2_rn(lo, hi);
    return *(uint32_t*)&h;
}
// mma.sync m16n8k16 f16 -> f32
__device__ __forceinline__ void mma_f16(float c[4],
                                        uint32_t a0, uint32_t a1, uint32_t a2, uint32_t a3,
                                        uint32_t b0, uint32_t b1) {
    asm volatile(
        "mma.sync.aligned.m16n8k16.row.col.f32.f16.f16.f32 "
        "{%0,%1,%2,%3}, {%4,%5,%6,%7}, {%8,%9}, {%0,%1,%2,%3};"
        : "+f"(c[0]), "+f"(c[1]), "+f"(c[2]), "+f"(c[3])
        : "r"(a0), "r"(a1), "r"(a2), "r"(a3), "r"(b0), "r"(b1));
}

// ---------------------------------------------------------------------------
// prepass: fp32 -> fp16 copies of x, qkv_w, proj_w
// ---------------------------------------------------------------------------
__global__ void half_prep(const float* __restrict__ x, const float* __restrict__ w,
                          const float* __restrict__ pw)
{
    int y = blockIdx.y;
    const float4* src;
    uint2* dst;
    long n4;
    if (y == 0)      { src = (const float4*)x;  dst = (uint2*)g_Xh;  n4 = (long)MTOT*BDIM/4; }
    else if (y == 1) { src = (const float4*)w;  dst = (uint2*)g_Wh;  n4 = (long)3*BDIM*BDIM/4; }
    else             { src = (const float4*)pw; dst = (uint2*)g_PWh; n4 = (long)BDIM*BDIM/4; }
    long stride = (long)gridDim.x * blockDim.x;
    for (long i = (long)blockIdx.x*blockDim.x + threadIdx.x; i < n4; i += stride) {
        float4 v = src[i];
        uint2 u;
        u.x = packh2(v.x, v.y);
        u.y = packh2(v.z, v.w);
        dst[i] = u;
    }
}

// ---------------------------------------------------------------------------
// FP16 GEMM (mma.sync m16n8k16 + cp.async 3-stage): C = A @ W^T + bias
// block 128x128, Ktile 32 halves (64B/row payload, 80B stride = SA words),
// 256 threads, warp tile 64x32. Word-level smem indices IDENTICAL to the
// proven tf32 kernel; words now hold half2.
//   MODE 0: A=g_Xh, W=g_Wh,  epilogue -> half Q(scaled)/K/[Vt transposed]
//   MODE 1: A=g_O,  W=g_PWh, epilogue -> fp32 row-major C
// ---------------------------------------------------------------------------
#define SA 20
#define STG_OP (128*SA*4)        // 10240 B per operand per stage
#define STG    (2*STG_OP)
#define NST    3

template<int MODE>
__global__ __launch_bounds__(256, 2)
void gemm_h(const float* __restrict__ bias, float* __restrict__ Cout,
            int K, int Nout)
{
    extern __shared__ char smem[];
    uint32_t sbase = smem_u32(smem);
    const __half* Ab = (MODE == 1) ? (const __half*)g_O  : (const __half*)g_Xh;
    const __half* Wb = (MODE == 1) ? (const __half*)g_PWh : (const __half*)g_Wh;

    int tid = threadIdx.x, warp = tid >> 5, lane = tid & 31;
    int g = lane >> 2, t = lane & 3;
    int wm = (warp >> 2) * 64, wn = (warp & 3) * 32;
    int m0 = blockIdx.y * 128, n0 = blockIdx.x * 128;

    // cp.async: 2 A-chunks + 2 B-chunks (16B = 8 halves) per thread per stage
    const __half* asrc[2];
    const __half* bsrc[2];
    uint32_t doff[2];
    #pragma unroll
    for (int i = 0; i < 2; i++) {
        int cid = i*256 + tid;
        int row = cid >> 2, ch = cid & 3;
        doff[i] = (uint32_t)(row*SA*4 + ch*16);
        asrc[i] = Ab + (long)(m0 + row)*K + ch*8;
        bsrc[i] = Wb + (long)(n0 + row)*K + ch*8;
    }

    float acc[4][4][4];
    #pragma unroll
    for (int i = 0; i < 4; i++)
        #pragma unroll
        for (int j = 0; j < 4; j++)
            #pragma unroll
            for (int c = 0; c < 4; c++) acc[i][j][c] = 0.f;

    int niter = K >> 5;          // Ktile = 32 halves

    #pragma unroll
    for (int s = 0; s < 2; s++) {
        uint32_t db = sbase + s*STG;
        #pragma unroll
        for (int i = 0; i < 2; i++) {
            cp16(db + doff[i],          asrc[i] + s*32);
            cp16(db + STG_OP + doff[i], bsrc[i] + s*32);
        }
        asm volatile("cp.async.commit_group;" ::: "memory");
    }

    for (int it = 0; it < niter; ++it) {
        asm volatile("cp.async.wait_group 1;" ::: "memory");
        __syncthreads();

        int nx = it + 2;
        if (nx < niter) {
            uint32_t db = sbase + (nx % NST)*STG;
            long koff = (long)nx * 32;
            #pragma unroll
            for (int i = 0; i < 2; i++) {
                cp16(db + doff[i],          asrc[i] + koff);
                cp16(db + STG_OP + doff[i], bsrc[i] + koff);
            }
        }
        asm volatile("cp.async.commit_group;" ::: "memory");

        const uint32_t* as = (const uint32_t*)(smem + (it % NST)*STG);
        const uint32_t* bs = (const uint32_t*)(smem + (it % NST)*STG + STG_OP);

        #pragma unroll
        for (int kk = 0; kk < 16; kk += 8) {     // two k16 steps
            uint32_t af[4][4], bf[4][2];
            #pragma unroll
            for (int mt = 0; mt < 4; mt++) {
                int rw = wm + mt*16;
                af[mt][0] = as[(rw+g)*SA   + kk + t];
                af[mt][1] = as[(rw+g+8)*SA + kk + t];
                af[mt][2] = as[(rw+g)*SA   + kk + t + 4];
                af[mt][3] = as[(rw+g+8)*SA + kk + t + 4];
            }
            #pragma unroll
            for (int nt = 0; nt < 4; nt++) {
                int cw = wn + nt*8 + g;
                bf[nt][0] = bs[cw*SA + kk + t];
                bf[nt][1] = bs[cw*SA + kk + t + 4];
            }
            #pragma unroll
            for (int mt = 0; mt < 4; mt++)
                #pragma unroll
                for (int nt = 0; nt < 4; nt++)
                    mma_f16(acc[mt][nt], af[mt][0], af[mt][1], af[mt][2], af[mt][3],
                            bf[nt][0], bf[nt][1]);
        }
    }

    // epilogue
    #pragma unroll
    for (int mt = 0; mt < 4; mt++) {
        int rowA = m0 + wm + mt*16 + g;
        int rowB = rowA + 8;
        #pragma unroll
        for (int nt = 0; nt < 4; nt++) {
            int col = n0 + wn + nt*8 + 2*t;
            float b0v = bias[col], b1v = bias[col+1];
            float2 va = make_float2(acc[mt][nt][0] + b0v, acc[mt][nt][1] + b1v);
            float2 vb = make_float2(acc[mt][nt][2] + b0v, acc[mt][nt][3] + b1v);
            if (MODE == 0) {
                int which = col >> 10;
                int c = col & (BDIM - 1);
                int hh = c >> 6, d = c & 63;
                int bA = rowA >> 11, nA = rowA & (SEQ - 1);
                int bR = rowB >> 11, nR = rowB & (SEQ - 1);
                if (which == 0) {        // Q, fold softmax scale
                    va.x *= QK_SCALE; va.y *= QK_SCALE;
                    vb.x *= QK_SCALE; vb.y *= QK_SCALE;
                    *(uint32_t*)(g_Q + ((((long)bA*NH + hh)*SEQ) + nA)*HD + d) = packh2(va.x, va.y);
                    *(uint32_t*)(g_Q + ((((long)bR*NH + hh)*SEQ) + nR)*HD + d) = packh2(vb.x, vb.y);
                } else if (which == 1) { // K
                    *(uint32_t*)(g_K + ((((long)bA*NH + hh)*SEQ) + nA)*HD + d) = packh2(va.x, va.y);
                    *(uint32_t*)(g_K + ((((long)bR*NH + hh)*SEQ) + nR)*HD + d) = packh2(vb.x, vb.y);
                } else {                 // V transposed: [b,h,d,n]
                    __half* vt = g_Vt;
                    long baseA = (((long)bA*NH + hh)*HD);
                    long baseB = (((long)bR*NH + hh)*HD);
                    vt[(baseA + d  )*SEQ + nA] = __float2half_rn(va.x);
                    vt[(baseA + d+1)*SEQ + nA] = __float2half_rn(va.y);
                    vt[(baseB + d  )*SEQ + nR] = __float2half_rn(vb.x);
                    vt[(baseB + d+1)*SEQ + nR] = __float2half_rn(vb.y);
                }
            } else {
                *(float2*)(Cout + (long)rowA * Nout + col) = va;
                *(float2*)(Cout + (long)rowB * Nout + col) = vb;
            }
        }
    }
}

// ---------------------------------------------------------------------------
// FP16 flash attention: 8 warps x 32 q-rows (256 q-rows/CTA), 64-key tiles.
// S C-frag == PV A-frag (fp16 identity) -> no shuffle transpose. V read from
// g_Vt so V B-frags are contiguous half2. cp.async 3-stage, stride 68 words
// (68 mod 32 = 4 -> conflict-free for the (row*S + t) quad pattern).
// ---------------------------------------------------------------------------
#define AKS 68                       // smem row stride in 32-bit words
#define KBY (64*AKS*4)               // 17408 B (64 rows)
#define ABUF (2*KBY)                 // K + V per stage
#define ANST 3

__global__ __launch_bounds__(256, 1)
void attn_h()
{
    extern __shared__ __align__(16) char dsm[];

    int tid  = threadIdx.x;
    int lane = tid & 31, warp = tid >> 5;      // warp 0..7
    int g = lane >> 2, t = lane & 3;
    int b = blockIdx.z, h = blockIdx.y;
    const __half* Qb  = g_Q  + ((long)(b*NH + h)) * SEQ * HD;
    const __half* Kb  = g_K  + ((long)(b*NH + h)) * SEQ * HD;
    const __half* Vtb = g_Vt + ((long)(b*NH + h)) * HD * SEQ;

    int qn = blockIdx.x * 256 + warp * 32;

    // cp.async staging: 512 chunks per operand / 256 threads = 2 each
    uint32_t sb = smem_u32(dsm);
    uint32_t kdo[2], vdo[2];
    const __half* ksrc[2];
    const __half* vsrc[2];
    #pragma unroll
    for (int i = 0; i < 2; i++) {
        int cid = i*256 + tid;
        int row = cid >> 3, ch = cid & 7;          // row 0..63, 8x16B chunks
        kdo[i] = (uint32_t)(row*AKS*4 + ch*16);
        vdo[i] = kdo[i] + KBY;
        ksrc[i] = Kb  + (long)row*HD  + ch*8;      // advances by 64*HD per tile
        vsrc[i] = Vtb + (long)row*SEQ + ch*8;      // advances by 64 per tile
    }

    // Q fragments (2 m-tiles of 16 rows), half2 words straight from gmem
    uint32_t qf[4][2][4];
    #pragma unroll
    for (int mt = 0; mt < 2; mt++) {
        const uint32_t* q0 = (const uint32_t*)(Qb + (long)(qn + mt*16 + g) * HD);
        const uint32_t* q1 = (const uint32_t*)(Qb + (long)(qn + mt*16 + g + 8) * HD);
        #pragma unroll
        for (int kk = 0; kk < 4; kk++) {
            qf[kk][mt][0] = q0[kk*8 + t];
            qf[kk][mt][1] = q1[kk*8 + t];
            qf[kk][mt][2] = q0[kk*8 + t + 4];
            qf[kk][mt][3] = q1[kk*8 + t + 4];
        }
    }

    float oacc[2][8][4];
    #pragma unroll
    for (int mt = 0; mt < 2; mt++)
        #pragma unroll
        for (int i = 0; i < 8; i++)
            #pragma unroll
            for (int j = 0; j < 4; j++) oacc[mt][i][j] = 0.f;
    float mA[2] = {-1e30f, -1e30f}, mB[2] = {-1e30f, -1e30f};
    float lA[2] = {0.f, 0.f},       lB[2] = {0.f, 0.f};

    // prologue: stages 0,1
    #pragma unroll
    for (int s = 0; s < 2; s++) {
        uint32_t so = (uint32_t)s * ABUF;
        #pragma unroll
        for (int i = 0; i < 2; i++) {
            cp16(sb + so + kdo[i], ksrc[i] + (long)s*64*HD);
            cp16(sb + so + vdo[i], vsrc[i] + s*64);
        }
        asm volatile("cp.async.commit_group;" ::: "memory");
    }

    const int NT = SEQ/64;
    for (int kt = 0; kt < NT; ++kt) {
        asm volatile("cp.async.wait_group 1;" ::: "memory");
        __syncthreads();

        if (kt + 2 < NT) {
            uint32_t so = (uint32_t)((kt+2) % ANST) * ABUF;
            #pragma unroll
            for (int i = 0; i < 2; i++) {
                cp16(sb + so + kdo[i], ksrc[i] + (long)(kt+2)*64*HD);
                cp16(sb + so + vdo[i], vsrc[i] + (kt+2)*64);
            }
        }
        asm volatile("cp.async.commit_group;" ::: "memory");

        const uint32_t* Ks = (const uint32_t*)(dsm + (kt % ANST)*ABUF);
        const uint32_t* Vs = (const uint32_t*)(dsm + (kt % ANST)*ABUF + KBY);

        // S = Q @ K^T (log2 units): kk = 4 k16 steps over HD
        float sc[2][8][4];
        #pragma unroll
        for (int mt = 0; mt < 2; mt++)
            #pragma unroll
            for (int i = 0; i < 8; i++)
                #pragma unroll
                for (int j = 0; j < 4; j++) sc[mt][i][j] = 0.f;
        #pragma unroll
        for (int kk = 0; kk < 4; kk++) {
            #pragma unroll
            for (int nt = 0; nt < 8; nt++) {
                uint32_t b0 = Ks[(nt*8+g)*AKS + kk*8 + t];
                uint32_t b1 = Ks[(nt*8+g)*AKS + kk*8 + t + 4];
                mma_f16(sc[0][nt], qf[kk][0][0], qf[kk][0][1], qf[kk][0][2], qf[kk][0][3], b0, b1);
                mma_f16(sc[1][nt], qf[kk][1][0], qf[kk][1][1], qf[kk][1][2], qf[kk][1][3], b0, b1);
            }
        }

        // online softmax per m-tile
        #pragma unroll
        for (int mt = 0; mt < 2; mt++) {
            float mlA = -1e30f, mlB = -1e30f;
            #pragma unroll
            for (int nt = 0; nt < 8; nt++) {
                mlA = fmaxf(mlA, fmaxf(sc[mt][nt][0], sc[mt][nt][1]));
                mlB = fmaxf(mlB, fmaxf(sc[mt][nt][2], sc[mt][nt][3]));
            }
            mlA = fmaxf(mlA, __shfl_xor_sync(0xffffffffu, mlA, 1));
            mlA = fmaxf(mlA, __shfl_xor_sync(0xffffffffu, mlA, 2));
            mlB = fmaxf(mlB, __shfl_xor_sync(0xffffffffu, mlB, 1));
            mlB = fmaxf(mlB, __shfl_xor_sync(0xffffffffu, mlB, 2));
            float mnA = fmaxf(mA[mt], mlA), mnB = fmaxf(mB[mt], mlB);
            float cA = ex2f(mA[mt] - mnA), cB = ex2f(mB[mt] - mnB);
            lA[mt] *= cA; lB[mt] *= cB;
            #pragma unroll
            for (int nt = 0; nt < 8; nt++) {
                oacc[mt][nt][0] *= cA; oacc[mt][nt][1] *= cA;
                oacc[mt][nt][2] *= cB; oacc[mt][nt][3] *= cB;
            }
            #pragma unroll
            for (int nt = 0; nt < 8; nt++) {
                float p0 = ex2f(sc[mt][nt][0] - mnA);
                float p1 = ex2f(sc[mt][nt][1] - mnA);
                float p2 = ex2f(sc[mt][nt][2] - mnB);
                float p3 = ex2f(sc[mt][nt][3] - mnB);
                lA[mt] += p0 + p1; lB[mt] += p2 + p3;
                sc[mt][nt][0] = p0; sc[mt][nt][1] = p1;
                sc[mt][nt][2] = p2; sc[mt][nt][3] = p3;
            }
            mA[mt] = mnA; mB[mt] = mnB;
        }

        // O += P @ V : S C-frag IS the PV A-frag (pack to half2, no shuffle).
        // k16 step kk covers keys kk*16..kk*16+15 = col-groups 2kk, 2kk+1.
        #pragma unroll
        for (int kk = 0; kk < 4; kk++) {
            uint32_t Af[2][4];
            #pragma unroll
            for (int mt = 0; mt < 2; mt++) {
                Af[mt][0] = packh2(sc[mt][2*kk][0],   sc[mt][2*kk][1]);
                Af[mt][1] = packh2(sc[mt][2*kk][2],   sc[mt][2*kk][3]);
                Af[mt][2] = packh2(sc[mt][2*kk+1][0], sc[mt][2*kk+1][1]);
                Af[mt][3] = packh2(sc[mt][2*kk+1][2], sc[mt][2*kk+1][3]);
            }
            #pragma unroll
            for (int nt = 0; nt < 8; nt++) {
                uint32_t b0 = Vs[(nt*8+g)*AKS + kk*8 + t];
                uint32_t b1 = Vs[(nt*8+g)*AKS + kk*8 + t + 4];
                mma_f16(oacc[0][nt], Af[0][0], Af[0][1], Af[0][2], Af[0][3], b0, b1);
                mma_f16(oacc[1][nt], Af[1][0], Af[1][1], Af[1][2], Af[1][3], b0, b1);
            }
        }
    }

    // finalize: quad-reduce l, normalize, write half2 to g_O [n][h*64+d]
    #pragma unroll
    for (int mt = 0; mt < 2; mt++) {
        float la = lA[mt], lb = lB[mt];
        la += __shfl_xor_sync(0xffffffffu, la, 1);
        la += __shfl_xor_sync(0xffffffffu, la, 2);
        lb += __shfl_xor_sync(0xffffffffu, lb, 1);
        lb += __shfl_xor_sync(0xffffffffu, lb, 2);
        float iA = 1.f / la, iB = 1.f / lb;

        __half* OA = g_O + ((long)(b*SEQ) + qn + mt*16 + g) * BDIM + h*HD;
        __half* OB = OA + 8*BDIM;
        #pragma unroll
        for (int nt = 0; nt < 8; nt++) {
            int c = nt*8 + 2*t;
            *(uint32_t*)(OA + c) = packh2(oacc[mt][nt][0]*iA, oacc[mt][nt][1]*iA);
            *(uint32_t*)(OB + c) = packh2(oacc[mt][nt][2]*iB, oacc[mt][nt][3]*iB);
        }
    }
}

// ---------------------------------------------------------------------------
extern "C" void kernel_launch(void* const* d_in, const int* in_sizes, int n_in,
                              void* d_out, int out_size)
{
    const float* x      = (const float*)d_in[0];
    const float* qkv_w  = (const float*)d_in[1];
    const float* qkv_b  = (const float*)d_in[2];
    const float* proj_w = (const float*)d_in[3];
    const float* proj_b = (const float*)d_in[4];
    float* out = (float*)d_out;

    int shmem  = NST * STG;      // 61440
    int ashmem = ANST * ABUF;    // 104448
    cudaFuncSetAttribute(gemm_h<0>, cudaFuncAttributeMaxDynamicSharedMemorySize, shmem);
    cudaFuncSetAttribute(gemm_h<1>, cudaFuncAttributeMaxDynamicSharedMemorySize, shmem);
    cudaFuncSetAttribute(attn_h, cudaFuncAttributeMaxDynamicSharedMemorySize, ashmem);

    half_prep<<<dim3(1024, 3), 256>>>(x, qkv_w, proj_w);

    dim3 g_qkv(3*BDIM/128, MTOT/128);   // (24, 32)
    gemm_h<0><<<g_qkv, 256, shmem>>>(qkv_b, nullptr, BDIM, 3*BDIM);

    dim3 g_attn(SEQ/256, NH, BB);       // (8, 16, 2)
    attn_h<<<g_attn, 256, ashmem>>>();

    dim3 g_proj(BDIM/128, MTOT/128);    // (8, 32)
    gemm_h<1><<<g_proj, 256, shmem>>>(proj_b, out, BDIM, BDIM);
}

// round 9
// speedup vs baseline: 9.1353x; 1.1476x over previous
#include <cuda_runtime.h>
#include <cuda_fp16.h>
#include <cstdint>

#define BDIM 1024
#define NH 16
#define HD 64
#define BB 2
#define SEQ 2048
#define MTOT (BB*SEQ)
#define QK_SCALE 0.1803368801111204f   // 0.125 * log2(e)

// scratch (device globals — allocation-guard safe). Referenced ONLY from
// device code (host-passing gives host shadow addrs — the R4/R5 bug).
__device__ __half g_Q [(long)BB*NH*SEQ*HD];     // Q pre-scaled by QK_SCALE
__device__ __half g_K [(long)BB*NH*SEQ*HD];
__device__ __half g_Vt[(long)BB*NH*HD*SEQ];     // V transposed: [b,h,d,n]
__device__ __half g_O [(long)MTOT*BDIM];        // attention out, head-concat
__device__ __half g_Xh[(long)MTOT*BDIM];
__device__ __half g_Wh[(long)3*BDIM*BDIM];
__device__ __half g_PWh[(long)BDIM*BDIM];

// ---------------------------------------------------------------------------
// helpers
// ---------------------------------------------------------------------------
__device__ __forceinline__ float ex2f(float x) {
    float y;
    asm("ex2.approx.ftz.f32 %0, %1;" : "=f"(y) : "f"(x));
    return y;
}
__device__ __forceinline__ uint32_t smem_u32(const void* p) {
    uint32_t a;
    asm("{ .reg .u64 t; cvta.to.shared.u64 t, %1; cvt.u32.u64 %0, t; }" : "=r"(a) : "l"(p));
    return a;
}
__device__ __forceinline__ void cp16(uint32_t dst, const void* src) {
    asm volatile("cp.async.cg.shared.global [%0], [%1], 16;" :: "r"(dst), "l"(src) : "memory");
}
__device__ __forceinline__ uint32_t packh2(float lo, float hi) {
    __half2 h = __floats2half2_rn(lo, hi);
    return *(uint32_t*)&h;
}
__device__ __forceinline__ void ldsm4(uint32_t* r, uint32_t addr) {
    asm volatile("ldmatrix.sync.aligned.m8n8.x4.shared.b16 {%0,%1,%2,%3}, [%4];"
                 : "=r"(r[0]), "=r"(r[1]), "=r"(r[2]), "=r"(r[3]) : "r"(addr));
}
// mma.sync m16n8k16 f16 -> f32
__device__ __forceinline__ void mma_f16(float c[4],
                                        uint32_t a0, uint32_t a1, uint32_t a2, uint32_t a3,
                                        uint32_t b0, uint32_t b1) {
    asm volatile(
        "mma.sync.aligned.m16n8k16.row.col.f32.f16.f16.f32 "
        "{%0,%1,%2,%3}, {%4,%5,%6,%7}, {%8,%9}, {%0,%1,%2,%3};"
        : "+f"(c[0]), "+f"(c[1]), "+f"(c[2]), "+f"(c[3])
        : "r"(a0), "r"(a1), "r"(a2), "r"(a3), "r"(b0), "r"(b1));
}

// ---------------------------------------------------------------------------
// prepass: fp32 -> fp16 copies of x, qkv_w, proj_w
// ---------------------------------------------------------------------------
__global__ void half_prep(const float* __restrict__ x, const float* __restrict__ w,
                          const float* __restrict__ pw)
{
    int y = blockIdx.y;
    const float4* src;
    uint2* dst;
    long n4;
    if (y == 0)      { src = (const float4*)x;  dst = (uint2*)g_Xh;  n4 = (long)MTOT*BDIM/4; }
    else if (y == 1) { src = (const float4*)w;  dst = (uint2*)g_Wh;  n4 = (long)3*BDIM*BDIM/4; }
    else             { src = (const float4*)pw; dst = (uint2*)g_PWh; n4 = (long)BDIM*BDIM/4; }
    long stride = (long)gridDim.x * blockDim.x;
    for (long i = (long)blockIdx.x*blockDim.x + threadIdx.x; i < n4; i += stride) {
        float4 v = src[i];
        uint2 u;
        u.x = packh2(v.x, v.y);
        u.y = packh2(v.z, v.w);
        dst[i] = u;
    }
}

// ---------------------------------------------------------------------------
// FP16 GEMM (mma.sync m16n8k16 + ldmatrix + cp.async 3-stage, SW128 smem):
// C = A @ W^T + bias. block 128x128, Ktile 64 halves (128B rows), 256 thr,
// warp tile 64x32. Per k16: 4 A-ldsm.x4 + 2 B-ldsm.x4 + 16 MMA.
//   MODE 0: A=g_Xh, W=g_Wh,  epilogue -> half Q(scaled)/K/[Vt transposed]
//   MODE 1: A=g_O,  W=g_PWh, epilogue -> fp32 row-major C
// ---------------------------------------------------------------------------
#define STG_OP 16384             // 128 rows x 128B
#define STG    32768
#define NST    3                 // 96 KB

template<int MODE>
__global__ __launch_bounds__(256, 2)
void gemm_h(const float* __restrict__ bias, float* __restrict__ Cout,
            int K, int Nout)
{
    extern __shared__ char smem[];
    uint32_t sbase = smem_u32(smem);
    const __half* Ab = (MODE == 1) ? (const __half*)g_O  : (const __half*)g_Xh;
    const __half* Wb = (MODE == 1) ? (const __half*)g_PWh : (const __half*)g_Wh;

    int tid = threadIdx.x, warp = tid >> 5, lane = tid & 31;
    int g = lane >> 2, t = lane & 3;
    int wm = (warp >> 2) * 64, wn = (warp & 3) * 32;
    int m0 = blockIdx.y * 128, n0 = blockIdx.x * 128;

    // cp.async: 4 A-chunks + 4 B-chunks (16B) per thread per stage (SW128)
    const __half* asrc[4];
    const __half* bsrc[4];
    uint32_t doff[4];
    #pragma unroll
    for (int i = 0; i < 4; i++) {
        int cid = i*256 + tid;              // 0..1023
        int row = cid >> 3, ch = cid & 7;
        doff[i] = (uint32_t)(row*128 + ((ch ^ (row & 7)) << 4));
        asrc[i] = Ab + (long)(m0 + row)*K + ch*8;
        bsrc[i] = Wb + (long)(n0 + row)*K + ch*8;
    }

    // ldmatrix lane addressing: r = base + (lane&15); chunk = 2kk + (lane>>4)
    int lr16 = lane & 15;
    uint32_t hs = (uint32_t)(lane >> 4);
    uint32_t cx = (uint32_t)(lane & 7);     // r&7 for all tiles (bases %16==0)
    uint32_t ar128[4], br128[2];
    #pragma unroll
    for (int mt = 0; mt < 4; mt++) ar128[mt] = (uint32_t)(wm + mt*16 + lr16) * 128u;
    #pragma unroll
    for (int p = 0; p < 2; p++)    br128[p] = (uint32_t)(wn + p*16 + lr16) * 128u;

    float acc[4][4][4];
    #pragma unroll
    for (int i = 0; i < 4; i++)
        #pragma unroll
        for (int j = 0; j < 4; j++)
            #pragma unroll
            for (int c = 0; c < 4; c++) acc[i][j][c] = 0.f;

    int niter = K >> 6;          // Ktile = 64 halves

    #pragma unroll
    for (int s = 0; s < 2; s++) {
        uint32_t db = sbase + s*STG;
        #pragma unroll
        for (int i = 0; i < 4; i++) {
            cp16(db + doff[i],          asrc[i] + s*64);
            cp16(db + STG_OP + doff[i], bsrc[i] + s*64);
        }
        asm volatile("cp.async.commit_group;" ::: "memory");
    }

    for (int it = 0; it < niter; ++it) {
        asm volatile("cp.async.wait_group 1;" ::: "memory");
        __syncthreads();

        int nx = it + 2;
        if (nx < niter) {
            uint32_t db = sbase + (nx % NST)*STG;
            long koff = (long)nx * 64;
            #pragma unroll
            for (int i = 0; i < 4; i++) {
                cp16(db + doff[i],          asrc[i] + koff);
                cp16(db + STG_OP + doff[i], bsrc[i] + koff);
            }
        }
        asm volatile("cp.async.commit_group;" ::: "memory");

        uint32_t sA = sbase + (it % NST)*STG;
        uint32_t sB = sA + STG_OP;

        #pragma unroll
        for (int kk = 0; kk < 4; kk++) {    // 4 k16 steps
            uint32_t sw = ((2u*kk + hs) ^ cx) << 4;
            uint32_t af[4][4], bf[2][4];
            #pragma unroll
            for (int mt = 0; mt < 4; mt++) ldsm4(af[mt], sA + ar128[mt] + sw);
            #pragma unroll
            for (int p = 0; p < 2; p++)    ldsm4(bf[p], sB + br128[p] + sw);
            #pragma unroll
            for (int mt = 0; mt < 4; mt++) {
                #pragma unroll
                for (int p = 0; p < 2; p++) {
                    mma_f16(acc[mt][2*p],   af[mt][0], af[mt][1], af[mt][2], af[mt][3],
                            bf[p][0], bf[p][2]);
                    mma_f16(acc[mt][2*p+1], af[mt][0], af[mt][1], af[mt][2], af[mt][3],
                            bf[p][1], bf[p][3]);
                }
            }
        }
    }

    // epilogue (unchanged, proven)
    #pragma unroll
    for (int mt = 0; mt < 4; mt++) {
        int rowA = m0 + wm + mt*16 + g;
        int rowB = rowA + 8;
        #pragma unroll
        for (int nt = 0; nt < 4; nt++) {
            int col = n0 + wn + nt*8 + 2*t;
            float b0v = bias[col], b1v = bias[col+1];
            float2 va = make_float2(acc[mt][nt][0] + b0v, acc[mt][nt][1] + b1v);
            float2 vb = make_float2(acc[mt][nt][2] + b0v, acc[mt][nt][3] + b1v);
            if (MODE == 0) {
                int which = col >> 10;
                int c = col & (BDIM - 1);
                int hh = c >> 6, d = c & 63;
                int bA = rowA >> 11, nA = rowA & (SEQ - 1);
                int bR = rowB >> 11, nR = rowB & (SEQ - 1);
                if (which == 0) {
                    va.x *= QK_SCALE; va.y *= QK_SCALE;
                    vb.x *= QK_SCALE; vb.y *= QK_SCALE;
                    *(uint32_t*)(g_Q + ((((long)bA*NH + hh)*SEQ) + nA)*HD + d) = packh2(va.x, va.y);
                    *(uint32_t*)(g_Q + ((((long)bR*NH + hh)*SEQ) + nR)*HD + d) = packh2(vb.x, vb.y);
                } else if (which == 1) {
                    *(uint32_t*)(g_K + ((((long)bA*NH + hh)*SEQ) + nA)*HD + d) = packh2(va.x, va.y);
                    *(uint32_t*)(g_K + ((((long)bR*NH + hh)*SEQ) + nR)*HD + d) = packh2(vb.x, vb.y);
                } else {                 // V transposed: [b,h,d,n]
                    __half* vt = g_Vt;
                    long baseA = (((long)bA*NH + hh)*HD);
                    long baseB = (((long)bR*NH + hh)*HD);
                    vt[(baseA + d  )*SEQ + nA] = __float2half_rn(va.x);
                    vt[(baseA + d+1)*SEQ + nA] = __float2half_rn(va.y);
                    vt[(baseB + d  )*SEQ + nR] = __float2half_rn(vb.x);
                    vt[(baseB + d+1)*SEQ + nR] = __float2half_rn(vb.y);
                }
            } else {
                *(float2*)(Cout + (long)rowA * Nout + col) = va;
                *(float2*)(Cout + (long)rowB * Nout + col) = vb;
            }
        }
    }
}

// ---------------------------------------------------------------------------
// FP16 flash attention: 8 warps x 32 q-rows, 64-key tiles, SW128 K/Vt smem
// tiles (64 rows x 128B), ldmatrix fragment loads, cp.async 3-stage.
// S C-frag == PV A-frag identity (no transpose shuffle).
// ---------------------------------------------------------------------------
#define KBY 8192                     // 64 rows x 128B
#define ABUF (2*KBY)
#define ANST 3                       // 48 KB

__global__ __launch_bounds__(256, 1)
void attn_h()
{
    extern __shared__ __align__(16) char dsm[];

    int tid  = threadIdx.x;
    int lane = tid & 31, warp = tid >> 5;      // warp 0..7
    int g = lane >> 2, t = lane & 3;
    int b = blockIdx.z, h = blockIdx.y;
    const __half* Qb  = g_Q  + ((long)(b*NH + h)) * SEQ * HD;
    const __half* Kb  = g_K  + ((long)(b*NH + h)) * SEQ * HD;
    const __half* Vtb = g_Vt + ((long)(b*NH + h)) * HD * SEQ;

    int qn = blockIdx.x * 256 + warp * 32;

    // cp.async staging: 512 chunks per operand, 2 per thread (SW128)
    uint32_t sb = smem_u32(dsm);
    uint32_t kdo[2];
    const __half* ksrc[2];
    const __half* vsrc[2];
    #pragma unroll
    for (int i = 0; i < 2; i++) {
        int cid = i*256 + tid;
        int row = cid >> 3, ch = cid & 7;          // row 0..63
        kdo[i] = (uint32_t)(row*128 + ((ch ^ (row & 7)) << 4));
        ksrc[i] = Kb  + (long)row*HD  + ch*8;      // +64*HD per tile
        vsrc[i] = Vtb + (long)row*SEQ + ch*8;      // +64 per tile
    }

    // ldmatrix addressing
    int lr16 = lane & 15;
    uint32_t hs = (uint32_t)(lane >> 4);
    uint32_t cx = (uint32_t)(lane & 7);
    uint32_t r128[4];
    #pragma unroll
    for (int p = 0; p < 4; p++) r128[p] = (uint32_t)(p*16 + lr16) * 128u;

    // Q fragments (2 m-tiles of 16 rows), half2 words straight from gmem
    uint32_t qf[4][2][4];
    #pragma unroll
    for (int mt = 0; mt < 2; mt++) {
        const uint32_t* q0 = (const uint32_t*)(Qb + (long)(qn + mt*16 + g) * HD);
        const uint32_t* q1 = (const uint32_t*)(Qb + (long)(qn + mt*16 + g + 8) * HD);
        #pragma unroll
        for (int kk = 0; kk < 4; kk++) {
            qf[kk][mt][0] = q0[kk*8 + t];
            qf[kk][mt][1] = q1[kk*8 + t];
            qf[kk][mt][2] = q0[kk*8 + t + 4];
            qf[kk][mt][3] = q1[kk*8 + t + 4];
        }
    }

    float oacc[2][8][4];
    #pragma unroll
    for (int mt = 0; mt < 2; mt++)
        #pragma unroll
        for (int i = 0; i < 8; i++)
            #pragma unroll
            for (int j = 0; j < 4; j++) oacc[mt][i][j] = 0.f;
    float mA[2] = {-1e30f, -1e30f}, mB[2] = {-1e30f, -1e30f};
    float lA[2] = {0.f, 0.f},       lB[2] = {0.f, 0.f};

    #pragma unroll
    for (int s = 0; s < 2; s++) {
        uint32_t so = (uint32_t)s * ABUF;
        #pragma unroll
        for (int i = 0; i < 2; i++) {
            cp16(sb + so + kdo[i],       ksrc[i] + (long)s*64*HD);
            cp16(sb + so + KBY + kdo[i], vsrc[i] + s*64);
        }
        asm volatile("cp.async.commit_group;" ::: "memory");
    }

    const int NT = SEQ/64;
    for (int kt = 0; kt < NT; ++kt) {
        asm volatile("cp.async.wait_group 1;" ::: "memory");
        __syncthreads();

        if (kt + 2 < NT) {
            uint32_t so = (uint32_t)((kt+2) % ANST) * ABUF;
            #pragma unroll
            for (int i = 0; i < 2; i++) {
                cp16(sb + so + kdo[i],       ksrc[i] + (long)(kt+2)*64*HD);
                cp16(sb + so + KBY + kdo[i], vsrc[i] + (kt+2)*64);
            }
        }
        asm volatile("cp.async.commit_group;" ::: "memory");

        uint32_t sK = sb + (kt % ANST)*ABUF;
        uint32_t sV = sK + KBY;

        // S = Q @ K^T (log2 units)
        float sc[2][8][4];
        #pragma unroll
        for (int mt = 0; mt < 2; mt++)
            #pragma unroll
            for (int i = 0; i < 8; i++)
                #pragma unroll
                for (int j = 0; j < 4; j++) sc[mt][i][j] = 0.f;
        #pragma unroll
        for (int kk = 0; kk < 4; kk++) {
            uint32_t sw = ((2u*kk + hs) ^ cx) << 4;
            uint32_t kb[4][4];
            #pragma unroll
            for (int p = 0; p < 4; p++) ldsm4(kb[p], sK + r128[p] + sw);
            #pragma unroll
            for (int p = 0; p < 4; p++) {
                #pragma unroll
                for (int mt = 0; mt < 2; mt++) {
                    mma_f16(sc[mt][2*p],   qf[kk][mt][0], qf[kk][mt][1], qf[kk][mt][2], qf[kk][mt][3],
                            kb[p][0], kb[p][2]);
                    mma_f16(sc[mt][2*p+1], qf[kk][mt][0], qf[kk][mt][1], qf[kk][mt][2], qf[kk][mt][3],
                            kb[p][1], kb[p][3]);
                }
            }
        }

        // online softmax per m-tile
        #pragma unroll
        for (int mt = 0; mt < 2; mt++) {
            float mlA = -1e30f, mlB = -1e30f;
            #pragma unroll
            for (int nt = 0; nt < 8; nt++) {
                mlA = fmaxf(mlA, fmaxf(sc[mt][nt][0], sc[mt][nt][1]));
                mlB = fmaxf(mlB, fmaxf(sc[mt][nt][2], sc[mt][nt][3]));
            }
            mlA = fmaxf(mlA, __shfl_xor_sync(0xffffffffu, mlA, 1));
            mlA = fmaxf(mlA, __shfl_xor_sync(0xffffffffu, mlA, 2));
            mlB = fmaxf(mlB, __shfl_xor_sync(0xffffffffu, mlB, 1));
            mlB = fmaxf(mlB, __shfl_xor_sync(0xffffffffu, mlB, 2));
            float mnA = fmaxf(mA[mt], mlA), mnB = fmaxf(mB[mt], mlB);
            float cA = ex2f(mA[mt] - mnA), cB = ex2f(mB[mt] - mnB);
            lA[mt] *= cA; lB[mt] *= cB;
            #pragma unroll
            for (int nt = 0; nt < 8; nt++) {
                oacc[mt][nt][0] *= cA; oacc[mt][nt][1] *= cA;
                oacc[mt][nt][2] *= cB; oacc[mt][nt][3] *= cB;
            }
            #pragma unroll
            for (int nt = 0; nt < 8; nt++) {
                float p0 = ex2f(sc[mt][nt][0] - mnA);
                float p1 = ex2f(sc[mt][nt][1] - mnA);
                float p2 = ex2f(sc[mt][nt][2] - mnB);
                float p3 = ex2f(sc[mt][nt][3] - mnB);
                lA[mt] += p0 + p1; lB[mt] += p2 + p3;
                sc[mt][nt][0] = p0; sc[mt][nt][1] = p1;
                sc[mt][nt][2] = p2; sc[mt][nt][3] = p3;
            }
            mA[mt] = mnA; mB[mt] = mnB;
        }

        // O += P @ V : S C-frag IS the PV A-frag; V frags via ldmatrix
        #pragma unroll
        for (int kk = 0; kk < 4; kk++) {
            uint32_t sw = ((2u*kk + hs) ^ cx) << 4;
            uint32_t Af[2][4];
            #pragma unroll
            for (int mt = 0; mt < 2; mt++) {
                Af[mt][0] = packh2(sc[mt][2*kk][0],   sc[mt][2*kk][1]);
                Af[mt][1] = packh2(sc[mt][2*kk][2],   sc[mt][2*kk][3]);
                Af[mt][2] = packh2(sc[mt][2*kk+1][0], sc[mt][2*kk+1][1]);
                Af[mt][3] = packh2(sc[mt][2*kk+1][2], sc[mt][2*kk+1][3]);
            }
            uint32_t vb[4][4];
            #pragma unroll
            for (int p = 0; p < 4; p++) ldsm4(vb[p], sV + r128[p] + sw);
            #pragma unroll
            for (int p = 0; p < 4; p++) {
                #pragma unroll
                for (int mt = 0; mt < 2; mt++) {
                    mma_f16(oacc[mt][2*p],   Af[mt][0], Af[mt][1], Af[mt][2], Af[mt][3],
                            vb[p][0], vb[p][2]);
                    mma_f16(oacc[mt][2*p+1], Af[mt][0], Af[mt][1], Af[mt][2], Af[mt][3],
                            vb[p][1], vb[p][3]);
                }
            }
        }
    }

    // finalize
    #pragma unroll
    for (int mt = 0; mt < 2; mt++) {
        float la = lA[mt], lb = lB[mt];
        la += __shfl_xor_sync(0xffffffffu, la, 1);
        la += __shfl_xor_sync(0xffffffffu, la, 2);
        lb += __shfl_xor_sync(0xffffffffu, lb, 1);
        lb += __shfl_xor_sync(0xffffffffu, lb, 2);
        float iA = 1.f / la, iB = 1.f / lb;

        __half* OA = g_O + ((long)(b*SEQ) + qn + mt*16 + g) * BDIM + h*HD;
        __half* OB = OA + 8*BDIM;
        #pragma unroll
        for (int nt = 0; nt < 8; nt++) {
            int c = nt*8 + 2*t;
            *(uint32_t*)(OA + c) = packh2(oacc[mt][nt][0]*iA, oacc[mt][nt][1]*iA);
            *(uint32_t*)(OB + c) = packh2(oacc[mt][nt][2]*iB, oacc[mt][nt][3]*iB);
        }
    }
}

// ---------------------------------------------------------------------------
extern "C" void kernel_launch(void* const* d_in, const int* in_sizes, int n_in,
                              void* d_out, int out_size)
{
    const float* x      = (const float*)d_in[0];
    const float* qkv_w  = (const float*)d_in[1];
    const float* qkv_b  = (const float*)d_in[2];
    const float* proj_w = (const float*)d_in[3];
    const float* proj_b = (const float*)d_in[4];
    float* out = (float*)d_out;

    int shmem  = NST * STG;      // 98304
    int ashmem = ANST * ABUF;    // 49152
    cudaFuncSetAttribute(gemm_h<0>, cudaFuncAttributeMaxDynamicSharedMemorySize, shmem);
    cudaFuncSetAttribute(gemm_h<1>, cudaFuncAttributeMaxDynamicSharedMemorySize, shmem);
    cudaFuncSetAttribute(attn_h, cudaFuncAttributeMaxDynamicSharedMemorySize, ashmem);

    half_prep<<<dim3(1024, 3), 256>>>(x, qkv_w, proj_w);

    dim3 g_qkv(3*BDIM/128, MTOT/128);   // (24, 32)
    gemm_h<0><<<g_qkv, 256, shmem>>>(qkv_b, nullptr, BDIM, 3*BDIM);

    dim3 g_attn(SEQ/256, NH, BB);       // (8, 16, 2)
    attn_h<<<g_attn, 256, ashmem>>>();

    dim3 g_proj(BDIM/128, MTOT/128);    // (8, 32)
    gemm_h<1><<<g_proj, 256, shmem>>>(proj_b, out, BDIM, BDIM);
}